// round 1
// baseline (speedup 1.0000x reference)
#include <cuda_runtime.h>
#include <cuda_bf16.h>
#include <math.h>

#define USER_NUM 100000
#define ITEM_NUM 50000
#define NN 150000
#define NE 2400000
#define NBATCH 4096

// Scratch (device globals; allocation inside kernel_launch is forbidden)
__device__ float g_x[150016 * 128];    // current features
__device__ float g_h[150016 * 128];    // hs = (x@W) * dis[row]
__device__ float g_acc[150016 * 128];  // accumulator (init = hs)
__device__ float g_dis[150016];        // rsqrt(1+deg), also used as deg counter
__device__ float g_stats[512];         // [0:128) colsum, [128:256) colsq, [256:384) scale, [384:512) shift
__device__ float g_loss;

// ---------------- setup kernels ----------------

__global__ void k_zero() {
    int i = blockIdx.x * 256 + threadIdx.x;
    if (i < NN) g_dis[i] = 0.f;
    if (i < 256) g_stats[i] = 0.f;
    if (i == 0) g_loss = 0.f;
}

__global__ void k_zstats() { g_stats[threadIdx.x] = 0.f; }  // 256 threads

__global__ void k_deg(const int* __restrict__ dst) {
    int e = blockIdx.x * 256 + threadIdx.x;
    if (e < NE) atomicAdd(&g_dis[dst[e]], 1.f);
}

__global__ void k_dis() {
    int i = blockIdx.x * 256 + threadIdx.x;
    if (i < NN) g_dis[i] = rsqrtf(1.f + g_dis[i]);
}

__global__ void k_concat(const float* __restrict__ ue, const float* __restrict__ ie) {
    int i = blockIdx.x * 256 + threadIdx.x;
    if (i < NN * 64) g_x[i] = (i < USER_NUM * 64) ? ue[i] : ie[i - USER_NUM * 64];
}

// ---------------- GEMM: g_h = g_acc = (g_x @ W) * dis[row] ----------------
// Block: 64 rows x N cols, 256 threads. Each thread: 1 row, N/4 cols.
template <int K, int N>
__global__ __launch_bounds__(256) void k_gemm(const float* __restrict__ W) {
    __shared__ float Ws[64 * N];
    const int tid = threadIdx.x;
    const int row = blockIdx.x * 64 + (tid >> 2);
    const int cg = tid & 3;
    constexpr int NC = N / 4;
    float acc[NC];
#pragma unroll
    for (int c = 0; c < NC; c++) acc[c] = 0.f;
    const bool valid = row < NN;

    for (int kc = 0; kc < K; kc += 64) {
#pragma unroll
        for (int i = 0; i < (64 * N) / 256; i++) {
            int idx = tid + i * 256;
            Ws[idx] = W[kc * N + idx];  // W chunk is contiguous row-major
        }
        __syncthreads();
        if (valid) {
            const float* xr = g_x + (size_t)row * K + kc;
#pragma unroll 8
            for (int k = 0; k < 64; k++) {
                float xv = xr[k];
                const float4* wr = reinterpret_cast<const float4*>(Ws + k * N + cg * NC);
#pragma unroll
                for (int c = 0; c < NC / 4; c++) {
                    float4 w = wr[c];
                    acc[4 * c + 0] += xv * w.x;
                    acc[4 * c + 1] += xv * w.y;
                    acc[4 * c + 2] += xv * w.z;
                    acc[4 * c + 3] += xv * w.w;
                }
            }
        }
        __syncthreads();
    }
    if (valid) {
        float d = g_dis[row];
        float* ho = g_h + (size_t)row * N + cg * NC;
        float* ao = g_acc + (size_t)row * N + cg * NC;
#pragma unroll
        for (int c = 0; c < NC / 4; c++) {
            float4 v = make_float4(acc[4 * c] * d, acc[4 * c + 1] * d,
                                   acc[4 * c + 2] * d, acc[4 * c + 3] * d);
            *reinterpret_cast<float4*>(ho + 4 * c) = v;
            *reinterpret_cast<float4*>(ao + 4 * c) = v;
        }
    }
}

// ---------------- scatter: g_acc[dst] += g_h[src], vector reductions ----------------
template <int N>
__global__ __launch_bounds__(256) void k_scatter(const int* __restrict__ src,
                                                 const int* __restrict__ dst) {
    constexpr int L = N / 4;  // lanes per edge
    long long t = (long long)blockIdx.x * 256 + threadIdx.x;
    int e = (int)(t / L);
    int l = (int)(t % L);
    if (e >= NE) return;
    int s = src[e], d = dst[e];
    float4 v = *reinterpret_cast<const float4*>(g_h + (size_t)s * N + l * 4);
    float* a = g_acc + (size_t)d * N + l * 4;
    asm volatile("red.global.add.v4.f32 [%0], {%1,%2,%3,%4};"
                 :: "l"(a), "f"(v.x), "f"(v.y), "f"(v.z), "f"(v.w)
                 : "memory");
}

// ---------------- mid-layer finalize: v = dis*acc + b (in place) + BN column stats ----------------
__global__ __launch_bounds__(256) void k_final_mid(const float* __restrict__ b) {
    __shared__ float ssum[256], ssq[256];
    int tid = threadIdx.x;
    int col = tid & 127;
    int rh = tid >> 7;
    int row0 = blockIdx.x * 32;
    float bc = b[col];
    float sum = 0.f, sq = 0.f;
    int rend = min(row0 + 32, NN);
    for (int r = row0 + rh; r < rend; r += 2) {
        size_t o = (size_t)r * 128 + col;
        float v = fmaf(g_dis[r], g_acc[o], bc);
        g_acc[o] = v;
        sum += v;
        sq += v * v;
    }
    ssum[tid] = sum;
    ssq[tid] = sq;
    __syncthreads();
    if (tid < 128) {
        atomicAdd(&g_stats[col], ssum[tid] + ssum[tid + 128]);
        atomicAdd(&g_stats[128 + col], ssq[tid] + ssq[tid + 128]);
    }
}

__global__ void k_bnprep(const float* __restrict__ g, const float* __restrict__ beta) {
    int c = threadIdx.x;  // 128 threads
    float m = g_stats[c] * (1.f / NN);
    float var = g_stats[128 + c] * (1.f / NN) - m * m;
    float sc = g[c] * rsqrtf(var + 1e-5f);
    g_stats[256 + c] = sc;
    g_stats[384 + c] = beta[c] - m * sc;
}

// BN-affine + ReLU + row L2 norm, warp per row, write to g_x
__global__ __launch_bounds__(256) void k_bnapply() {
    int row = blockIdx.x * 8 + (threadIdx.x >> 5);
    int lane = threadIdx.x & 31;
    if (row >= NN) return;
    float4 v = *reinterpret_cast<const float4*>(g_acc + (size_t)row * 128 + lane * 4);
    float4 sc = *reinterpret_cast<const float4*>(g_stats + 256 + lane * 4);
    float4 sh = *reinterpret_cast<const float4*>(g_stats + 384 + lane * 4);
    float y0 = fmaxf(fmaf(v.x, sc.x, sh.x), 0.f);
    float y1 = fmaxf(fmaf(v.y, sc.y, sh.y), 0.f);
    float y2 = fmaxf(fmaf(v.z, sc.z, sh.z), 0.f);
    float y3 = fmaxf(fmaf(v.w, sc.w, sh.w), 0.f);
    float sq = y0 * y0 + y1 * y1 + y2 * y2 + y3 * y3;
#pragma unroll
    for (int o = 16; o; o >>= 1) sq += __shfl_xor_sync(0xffffffffu, sq, o);
    float inv = 1.f / fmaxf(sqrtf(sq), 1e-12f);
    float4 out = make_float4(y0 * inv, y1 * inv, y2 * inv, y3 * inv);
    *reinterpret_cast<float4*>(g_x + (size_t)row * 128 + lane * 4) = out;
}

// last-layer finalize: xout = dis*acc + b2 (scalar stores; xout is 4B-offset into d_out)
__global__ void k_final_out(const float* __restrict__ b2, float* __restrict__ xo) {
    int i = blockIdx.x * 256 + threadIdx.x;
    if (i >= NN * 64) return;
    int r = i >> 6, c = i & 63;
    xo[i] = fmaf(g_dis[r], g_acc[(size_t)r * 64 + c], b2[c]);
}

// BPR loss: warp per sample
__global__ __launch_bounds__(256) void k_loss(const float* __restrict__ xo,
                                              const int* __restrict__ uid,
                                              const int* __restrict__ pid,
                                              const int* __restrict__ nid) {
    int s = blockIdx.x * 8 + (threadIdx.x >> 5);
    int lane = threadIdx.x & 31;
    if (s >= NBATCH) return;
    const float* u = xo + (size_t)uid[s] * 64;
    const float* p = xo + (size_t)(USER_NUM + pid[s]) * 64;
    const float* nr = xo + (size_t)(USER_NUM + nid[s]) * 64;
    float ps = 0.f, ns = 0.f;
#pragma unroll
    for (int j = 0; j < 2; j++) {
        int c = lane + j * 32;
        float uv = u[c];
        ps += uv * p[c];
        ns += uv * nr[c];
    }
#pragma unroll
    for (int o = 16; o; o >>= 1) {
        ps += __shfl_xor_sync(0xffffffffu, ps, o);
        ns += __shfl_xor_sync(0xffffffffu, ns, o);
    }
    if (lane == 0) {
        float z = ps - ns;
        float ls = fminf(z, 0.f) - log1pf(expf(-fabsf(z)));  // log_sigmoid(z)
        atomicAdd(&g_loss, ls);
    }
}

__global__ void k_wloss(float* __restrict__ out) {
    out[0] = -g_loss * (1.f / NBATCH);
}

// ---------------- launch ----------------
extern "C" void kernel_launch(void* const* d_in, const int* in_sizes, int n_in,
                              void* d_out, int out_size) {
    const float* user_emb = (const float*)d_in[0];
    const float* item_emb = (const float*)d_in[1];
    const float* W0 = (const float*)d_in[2];
    const float* b0 = (const float*)d_in[3];
    const float* g0 = (const float*)d_in[4];
    const float* beta0 = (const float*)d_in[5];
    const float* W1 = (const float*)d_in[6];
    const float* b1 = (const float*)d_in[7];
    const float* g1 = (const float*)d_in[8];
    const float* beta1 = (const float*)d_in[9];
    const float* W2 = (const float*)d_in[10];
    const float* b2 = (const float*)d_in[11];
    const int* user_id = (const int*)d_in[12];
    const int* pos_item = (const int*)d_in[13];
    const int* neg_item = (const int*)d_in[14];
    const int* ei = (const int*)d_in[15];
    const int* src = ei;
    const int* dst = ei + NE;

    float* out = (float*)d_out;
    float* xout = out + 1;  // [rec_loss, x(150000x64)]

    // setup
    k_zero<<<(NN + 255) / 256, 256>>>();
    k_deg<<<(NE + 255) / 256, 256>>>(dst);
    k_dis<<<(NN + 255) / 256, 256>>>();
    k_concat<<<(NN * 64 + 255) / 256, 256>>>(user_emb, item_emb);

    const int GB = (NN + 63) / 64;  // gemm blocks

    // ---- layer 0: 64 -> 128 ----
    k_gemm<64, 128><<<GB, 256>>>(W0);
    k_scatter<128><<<(int)(((long long)NE * 32 + 255) / 256), 256>>>(src, dst);
    k_final_mid<<<(NN + 31) / 32, 256>>>(b0);
    k_bnprep<<<1, 128>>>(g0, beta0);
    k_bnapply<<<(NN + 7) / 8, 256>>>();

    // ---- layer 1: 128 -> 128 ----
    k_zstats<<<1, 256>>>();
    k_gemm<128, 128><<<GB, 256>>>(W1);
    k_scatter<128><<<(int)(((long long)NE * 32 + 255) / 256), 256>>>(src, dst);
    k_final_mid<<<(NN + 31) / 32, 256>>>(b1);
    k_bnprep<<<1, 128>>>(g1, beta1);
    k_bnapply<<<(NN + 7) / 8, 256>>>();

    // ---- layer 2: 128 -> 64 ----
    k_gemm<128, 64><<<GB, 256>>>(W2);
    k_scatter<64><<<(int)(((long long)NE * 16 + 255) / 256), 256>>>(src, dst);
    k_final_out<<<(NN * 64 + 255) / 256, 256>>>(b2, xout);

    // ---- loss ----
    k_loss<<<(NBATCH + 7) / 8, 256>>>(xout, user_id, pos_item, neg_item);
    k_wloss<<<1, 1>>>(out);
}

// round 4
// speedup vs baseline: 1.2449x; 1.2449x over previous
#include <cuda_runtime.h>
#include <cuda_bf16.h>
#include <math.h>

#define USER_NUM 100000
#define ITEM_NUM 50000
#define NN 150000
#define NE 2400000
#define NBATCH 4096
#define SCAN_B ((NN + 255) / 256)   // 586

// Scratch (device globals; allocation is forbidden).
// NOTE: device symbols are referenced ONLY inside kernels, never passed as
// host-side kernel arguments (that is UB and was the R3 failure suspect).
__device__ float g_x[150016 * 128];    // current features
__device__ float g_h[150016 * 128];    // hs = (x@W) * dis[row]
__device__ float g_acc[150016 * 128];  // conv output (pre-BN)
__device__ float g_dis[150016];        // rsqrt(1+deg)
__device__ int   g_degi[150016];
__device__ int   g_rows[150016 + 16];  // CSR row offsets (by dst)
__device__ int   g_cursor[150016];
__device__ int   g_part[1024];
__device__ int   g_csrc[NE];           // CSR column (src) ids
__device__ float g_stats[512];         // [0:128) colsum, [128:256) colsq, [256:384) scale, [384:512) shift
__device__ float g_loss;

// ---------------- setup ----------------

__global__ void k_zero() {
    int i = blockIdx.x * 256 + threadIdx.x;
    if (i < NN) g_degi[i] = 0;
    if (i < 256) g_stats[i] = 0.f;
    if (i == 0) g_loss = 0.f;
}

__global__ void k_zstats() { g_stats[threadIdx.x] = 0.f; }  // 256 threads

__global__ void k_deg(const int* __restrict__ dst) {
    int e = blockIdx.x * 256 + threadIdx.x;
    if (e < NE) atomicAdd(&g_degi[dst[e]], 1);
}

__global__ void k_dis() {
    int i = blockIdx.x * 256 + threadIdx.x;
    if (i < NN) g_dis[i] = rsqrtf(1.f + (float)g_degi[i]);
}

__global__ void k_concat(const float* __restrict__ ue, const float* __restrict__ ie) {
    int i = blockIdx.x * 256 + threadIdx.x;
    if (i < NN * 64) g_x[i] = (i < USER_NUM * 64) ? ue[i] : ie[i - USER_NUM * 64];
}

// ---------------- prefix scan (3 kernels) ----------------

__global__ void k_scan1() {
    __shared__ int s[256];
    int tid = threadIdx.x;
    int i = blockIdx.x * 256 + tid;
    int v = (i < NN) ? g_degi[i] : 0;
    s[tid] = v;
    __syncthreads();
    for (int off = 1; off < 256; off <<= 1) {
        int t = (tid >= off) ? s[tid - off] : 0;
        __syncthreads();
        s[tid] += t;
        __syncthreads();
    }
    if (i < NN) g_rows[i] = s[tid] - v;  // exclusive within block
    if (tid == 255) g_part[blockIdx.x] = s[255];
}

__global__ void k_scan2() {  // 1 block, 1024 threads
    __shared__ int s[1024];
    int tid = threadIdx.x;
    int v = (tid < SCAN_B) ? g_part[tid] : 0;
    s[tid] = v;
    __syncthreads();
    for (int off = 1; off < 1024; off <<= 1) {
        int t = (tid >= off) ? s[tid - off] : 0;
        __syncthreads();
        s[tid] += t;
        __syncthreads();
    }
    if (tid < SCAN_B) g_part[tid] = s[tid] - v;  // exclusive
}

__global__ void k_scan3() {
    int i = blockIdx.x * 256 + threadIdx.x;
    if (i < NN) {
        int r = g_rows[i] + g_part[i >> 8];
        g_rows[i] = r;
        g_cursor[i] = r;
    }
    if (i == NN) g_rows[NN] = NE;
}

__global__ void k_csrfill(const int* __restrict__ src, const int* __restrict__ dst) {
    int e = blockIdx.x * 256 + threadIdx.x;
    if (e < NE) {
        int d = dst[e];
        int p = atomicAdd(&g_cursor[d], 1);
        g_csrc[p] = src[e];
    }
}

// ---------------- GEMM: g_h = (g_x @ W) * dis[row] ----------------
template <int K, int N>
__global__ __launch_bounds__(256) void k_gemm(const float* __restrict__ W) {
    __shared__ float Ws[64 * N];
    const int tid = threadIdx.x;
    const int row = blockIdx.x * 64 + (tid >> 2);
    const int cg = tid & 3;
    constexpr int NC = N / 4;
    float acc[NC];
#pragma unroll
    for (int c = 0; c < NC; c++) acc[c] = 0.f;
    const bool valid = row < NN;

    for (int kc = 0; kc < K; kc += 64) {
#pragma unroll
        for (int i = 0; i < (64 * N) / 256; i++) {
            int idx = tid + i * 256;
            Ws[idx] = W[kc * N + idx];
        }
        __syncthreads();
        if (valid) {
            const float* xr = g_x + (size_t)row * K + kc;
#pragma unroll 8
            for (int k = 0; k < 64; k++) {
                float xv = xr[k];
                const float4* wr = reinterpret_cast<const float4*>(Ws + k * N + cg * NC);
#pragma unroll
                for (int c = 0; c < NC / 4; c++) {
                    float4 w = wr[c];
                    acc[4 * c + 0] += xv * w.x;
                    acc[4 * c + 1] += xv * w.y;
                    acc[4 * c + 2] += xv * w.z;
                    acc[4 * c + 3] += xv * w.w;
                }
            }
        }
        __syncthreads();
    }
    if (valid) {
        float d = g_dis[row];
        float* ho = g_h + (size_t)row * N + cg * NC;
#pragma unroll
        for (int c = 0; c < NC / 4; c++) {
            *reinterpret_cast<float4*>(ho + 4 * c) =
                make_float4(acc[4 * c] * d, acc[4 * c + 1] * d,
                            acc[4 * c + 2] * d, acc[4 * c + 3] * d);
        }
    }
}

// ---------------- CSR aggregation ----------------
// out[n] = dis[n]*(h[n] + sum_{e->n} h[src_e]) + b
// FINAL=false: writes g_acc (device symbol, referenced internally), float4.
// FINAL=true : writes `out` (harness pointer, only 4B aligned), scalar stores.
template <int N, bool FINAL>
__global__ __launch_bounds__(256) void k_agg(const float* __restrict__ b,
                                             float* __restrict__ out) {
    constexpr int VE = N / 32;  // 4 (N=128) or 2 (N=64)
    const int lane = threadIdx.x & 31;
    const int warp = threadIdx.x >> 5;
    float bv[VE];
#pragma unroll
    for (int i = 0; i < VE; i++) bv[i] = b[lane * VE + i];

    for (int node = blockIdx.x * 8 + warp; node < NN; node += gridDim.x * 8) {
        float acc[VE];
        {
            const float* hr = g_h + (size_t)node * N + lane * VE;
            if constexpr (VE == 4) {
                float4 t = *(const float4*)hr;
                acc[0] = t.x; acc[1] = t.y; acc[2] = t.z; acc[3] = t.w;
            } else {
                float2 t = *(const float2*)hr;
                acc[0] = t.x; acc[1] = t.y;
            }
        }
        int beg = g_rows[node], end = g_rows[node + 1];
        int e = beg;
        for (; e + 1 < end; e += 2) {  // 2-edge unroll for MLP
            int s0 = g_csrc[e], s1 = g_csrc[e + 1];
            const float* v0 = g_h + (size_t)s0 * N + lane * VE;
            const float* v1 = g_h + (size_t)s1 * N + lane * VE;
            if constexpr (VE == 4) {
                float4 a = *(const float4*)v0;
                float4 c = *(const float4*)v1;
                acc[0] += a.x + c.x; acc[1] += a.y + c.y;
                acc[2] += a.z + c.z; acc[3] += a.w + c.w;
            } else {
                float2 a = *(const float2*)v0;
                float2 c = *(const float2*)v1;
                acc[0] += a.x + c.x; acc[1] += a.y + c.y;
            }
        }
        if (e < end) {
            int s0 = g_csrc[e];
            const float* v0 = g_h + (size_t)s0 * N + lane * VE;
            if constexpr (VE == 4) {
                float4 a = *(const float4*)v0;
                acc[0] += a.x; acc[1] += a.y; acc[2] += a.z; acc[3] += a.w;
            } else {
                float2 a = *(const float2*)v0;
                acc[0] += a.x; acc[1] += a.y;
            }
        }
        float dd = g_dis[node];
        float v[VE];
#pragma unroll
        for (int i = 0; i < VE; i++) v[i] = fmaf(acc[i], dd, bv[i]);

        if constexpr (FINAL) {
            float* orow = out + (size_t)node * N + lane * VE;
#pragma unroll
            for (int i = 0; i < VE; i++) orow[i] = v[i];
        } else {
            float* orow = g_acc + (size_t)node * N + lane * VE;
            *(float4*)orow = make_float4(v[0], v[1], v[2], v[3]);
        }
    }
}

// ---------------- BN column stats over g_acc (R1-proven structure) ----------------
__global__ __launch_bounds__(256) void k_stats() {
    __shared__ float ssum[256], ssq[256];
    int tid = threadIdx.x;
    int col = tid & 127;
    int rh = tid >> 7;
    int row0 = blockIdx.x * 32;
    float sum = 0.f, sq = 0.f;
    int rend = min(row0 + 32, NN);
    for (int r = row0 + rh; r < rend; r += 2) {
        float v = g_acc[(size_t)r * 128 + col];
        sum += v;
        sq += v * v;
    }
    ssum[tid] = sum;
    ssq[tid] = sq;
    __syncthreads();
    if (tid < 128) {
        atomicAdd(&g_stats[col], ssum[tid] + ssum[tid + 128]);
        atomicAdd(&g_stats[128 + col], ssq[tid] + ssq[tid + 128]);
    }
}

// ---------------- BN prep + apply ----------------
__global__ void k_bnprep(const float* __restrict__ g, const float* __restrict__ beta) {
    int c = threadIdx.x;  // 128 threads
    float m = g_stats[c] * (1.f / NN);
    float var = g_stats[128 + c] * (1.f / NN) - m * m;
    float sc = g[c] * rsqrtf(var + 1e-5f);
    g_stats[256 + c] = sc;
    g_stats[384 + c] = beta[c] - m * sc;
}

__global__ __launch_bounds__(256) void k_bnapply() {
    int row = blockIdx.x * 8 + (threadIdx.x >> 5);
    int lane = threadIdx.x & 31;
    if (row >= NN) return;
    float4 v = *reinterpret_cast<const float4*>(g_acc + (size_t)row * 128 + lane * 4);
    float4 sc = *reinterpret_cast<const float4*>(g_stats + 256 + lane * 4);
    float4 sh = *reinterpret_cast<const float4*>(g_stats + 384 + lane * 4);
    float y0 = fmaxf(fmaf(v.x, sc.x, sh.x), 0.f);
    float y1 = fmaxf(fmaf(v.y, sc.y, sh.y), 0.f);
    float y2 = fmaxf(fmaf(v.z, sc.z, sh.z), 0.f);
    float y3 = fmaxf(fmaf(v.w, sc.w, sh.w), 0.f);
    float sq = y0 * y0 + y1 * y1 + y2 * y2 + y3 * y3;
#pragma unroll
    for (int o = 16; o; o >>= 1) sq += __shfl_xor_sync(0xffffffffu, sq, o);
    float inv = 1.f / fmaxf(sqrtf(sq), 1e-12f);
    *reinterpret_cast<float4*>(g_x + (size_t)row * 128 + lane * 4) =
        make_float4(y0 * inv, y1 * inv, y2 * inv, y3 * inv);
}

// ---------------- BPR loss ----------------
__global__ __launch_bounds__(256) void k_loss(const float* __restrict__ xo,
                                              const int* __restrict__ uid,
                                              const int* __restrict__ pid,
                                              const int* __restrict__ nid) {
    int s = blockIdx.x * 8 + (threadIdx.x >> 5);
    int lane = threadIdx.x & 31;
    if (s >= NBATCH) return;
    const float* u = xo + (size_t)uid[s] * 64;
    const float* p = xo + (size_t)(USER_NUM + pid[s]) * 64;
    const float* nr = xo + (size_t)(USER_NUM + nid[s]) * 64;
    float ps = 0.f, ns = 0.f;
#pragma unroll
    for (int j = 0; j < 2; j++) {
        int c = lane + j * 32;
        float uv = u[c];
        ps += uv * p[c];
        ns += uv * nr[c];
    }
#pragma unroll
    for (int o = 16; o; o >>= 1) {
        ps += __shfl_xor_sync(0xffffffffu, ps, o);
        ns += __shfl_xor_sync(0xffffffffu, ns, o);
    }
    if (lane == 0) {
        float z = ps - ns;
        float ls = fminf(z, 0.f) - log1pf(expf(-fabsf(z)));
        atomicAdd(&g_loss, ls);
    }
}

__global__ void k_wloss(float* __restrict__ out) {
    out[0] = -g_loss * (1.f / NBATCH);
}

// ---------------- launch ----------------
extern "C" void kernel_launch(void* const* d_in, const int* in_sizes, int n_in,
                              void* d_out, int out_size) {
    const float* user_emb = (const float*)d_in[0];
    const float* item_emb = (const float*)d_in[1];
    const float* W0 = (const float*)d_in[2];
    const float* b0 = (const float*)d_in[3];
    const float* g0 = (const float*)d_in[4];
    const float* beta0 = (const float*)d_in[5];
    const float* W1 = (const float*)d_in[6];
    const float* b1 = (const float*)d_in[7];
    const float* g1 = (const float*)d_in[8];
    const float* beta1 = (const float*)d_in[9];
    const float* W2 = (const float*)d_in[10];
    const float* b2 = (const float*)d_in[11];
    const int* user_id = (const int*)d_in[12];
    const int* pos_item = (const int*)d_in[13];
    const int* neg_item = (const int*)d_in[14];
    const int* ei = (const int*)d_in[15];
    const int* src = ei;
    const int* dst = ei + NE;

    float* out = (float*)d_out;
    float* xout = out + 1;  // [rec_loss, x(150000x64)] -- only 4B aligned!

    const int EB = (NE + 255) / 256;
    const int AGGB = 2048;
    const int SB = (NN + 31) / 32;

    // setup + CSR build
    k_zero<<<(NN + 255) / 256, 256>>>();
    k_deg<<<EB, 256>>>(dst);
    k_dis<<<(NN + 255) / 256, 256>>>();
    k_concat<<<(NN * 64 + 255) / 256, 256>>>(user_emb, item_emb);
    k_scan1<<<SCAN_B, 256>>>();
    k_scan2<<<1, 1024>>>();
    k_scan3<<<SCAN_B + 1, 256>>>();
    k_csrfill<<<EB, 256>>>(src, dst);

    const int GB = (NN + 63) / 64;

    // ---- layer 0: 64 -> 128 ----
    k_gemm<64, 128><<<GB, 256>>>(W0);
    k_agg<128, false><<<AGGB, 256>>>(b0, nullptr);
    k_stats<<<SB, 256>>>();
    k_bnprep<<<1, 128>>>(g0, beta0);
    k_bnapply<<<(NN + 7) / 8, 256>>>();

    // ---- layer 1: 128 -> 128 ----
    k_zstats<<<1, 256>>>();
    k_gemm<128, 128><<<GB, 256>>>(W1);
    k_agg<128, false><<<AGGB, 256>>>(b1, nullptr);
    k_stats<<<SB, 256>>>();
    k_bnprep<<<1, 128>>>(g1, beta1);
    k_bnapply<<<(NN + 7) / 8, 256>>>();

    // ---- layer 2: 128 -> 64 ----
    k_gemm<128, 64><<<GB, 256>>>(W2);
    k_agg<64, true><<<AGGB, 256>>>(b2, xout);

    // ---- loss ----
    k_loss<<<(NBATCH + 7) / 8, 256>>>(xout, user_id, pos_item, neg_item);
    k_wloss<<<1, 1>>>(out);
}

// round 5
// speedup vs baseline: 1.2497x; 1.0039x over previous
#include <cuda_runtime.h>
#include <cuda_bf16.h>
#include <math.h>

#define USER_NUM 100000
#define ITEM_NUM 50000
#define NN 150000
#define NE 2400000
#define NBATCH 4096
#define SCAN_B ((NN + 255) / 256)   // 586

// Scratch (device globals; allocation is forbidden).
// NOTE: device symbols are referenced ONLY inside kernels, never passed as
// host-side kernel arguments (that is UB and was the R3 failure suspect).
__device__ float g_x[150016 * 128];    // current features
__device__ float g_h[150016 * 128];    // hs = (x@W) * dis[row]
__device__ float g_acc[150016 * 128];  // conv output (pre-BN)
__device__ float g_dis[150016];        // rsqrt(1+deg)
__device__ int   g_degi[150016];
__device__ int   g_rows[150016 + 16];  // CSR row offsets (by dst)
__device__ int   g_cursor[150016];
__device__ int   g_part[1024];
__device__ int   g_csrc[NE];           // CSR column (src) ids
__device__ float g_stats[512];         // [0:128) colsum, [128:256) colsq, [256:384) scale, [384:512) shift
__device__ float g_loss;

// ---------------- setup ----------------

__global__ void k_zero() {
    int i = blockIdx.x * 256 + threadIdx.x;
    if (i < NN) g_degi[i] = 0;
    if (i < 256) g_stats[i] = 0.f;
    if (i == 0) g_loss = 0.f;
}

__global__ void k_zstats() { g_stats[threadIdx.x] = 0.f; }  // 256 threads

__global__ void k_deg(const int* __restrict__ dst) {
    int e = blockIdx.x * 256 + threadIdx.x;
    if (e < NE) atomicAdd(&g_degi[dst[e]], 1);
}

__global__ void k_dis() {
    int i = blockIdx.x * 256 + threadIdx.x;
    if (i < NN) g_dis[i] = rsqrtf(1.f + (float)g_degi[i]);
}

__global__ void k_concat(const float* __restrict__ ue, const float* __restrict__ ie) {
    int i = blockIdx.x * 256 + threadIdx.x;
    if (i < NN * 64) g_x[i] = (i < USER_NUM * 64) ? ue[i] : ie[i - USER_NUM * 64];
}

// ---------------- prefix scan (3 kernels) ----------------

__global__ void k_scan1() {
    __shared__ int s[256];
    int tid = threadIdx.x;
    int i = blockIdx.x * 256 + tid;
    int v = (i < NN) ? g_degi[i] : 0;
    s[tid] = v;
    __syncthreads();
    for (int off = 1; off < 256; off <<= 1) {
        int t = (tid >= off) ? s[tid - off] : 0;
        __syncthreads();
        s[tid] += t;
        __syncthreads();
    }
    if (i < NN) g_rows[i] = s[tid] - v;  // exclusive within block
    if (tid == 255) g_part[blockIdx.x] = s[255];
}

__global__ void k_scan2() {  // 1 block, 1024 threads
    __shared__ int s[1024];
    int tid = threadIdx.x;
    int v = (tid < SCAN_B) ? g_part[tid] : 0;
    s[tid] = v;
    __syncthreads();
    for (int off = 1; off < 1024; off <<= 1) {
        int t = (tid >= off) ? s[tid - off] : 0;
        __syncthreads();
        s[tid] += t;
        __syncthreads();
    }
    if (tid < SCAN_B) g_part[tid] = s[tid] - v;  // exclusive
}

__global__ void k_scan3() {
    int i = blockIdx.x * 256 + threadIdx.x;
    if (i < NN) {
        int r = g_rows[i] + g_part[i >> 8];
        g_rows[i] = r;
        g_cursor[i] = r;
    }
    if (i == NN) g_rows[NN] = NE;
}

__global__ void k_csrfill(const int* __restrict__ src, const int* __restrict__ dst) {
    int e = blockIdx.x * 256 + threadIdx.x;
    if (e < NE) {
        int d = dst[e];
        int p = atomicAdd(&g_cursor[d], 1);
        g_csrc[p] = src[e];
    }
}

// ---------------- GEMM: g_h = (g_x @ W) * dis[row] ----------------
template <int K, int N>
__global__ __launch_bounds__(256) void k_gemm(const float* __restrict__ W) {
    __shared__ float Ws[64 * N];
    const int tid = threadIdx.x;
    const int row = blockIdx.x * 64 + (tid >> 2);
    const int cg = tid & 3;
    constexpr int NC = N / 4;
    float acc[NC];
#pragma unroll
    for (int c = 0; c < NC; c++) acc[c] = 0.f;
    const bool valid = row < NN;

    for (int kc = 0; kc < K; kc += 64) {
#pragma unroll
        for (int i = 0; i < (64 * N) / 256; i++) {
            int idx = tid + i * 256;
            Ws[idx] = W[kc * N + idx];
        }
        __syncthreads();
        if (valid) {
            const float* xr = g_x + (size_t)row * K + kc;
#pragma unroll 8
            for (int k = 0; k < 64; k++) {
                float xv = xr[k];
                const float4* wr = reinterpret_cast<const float4*>(Ws + k * N + cg * NC);
#pragma unroll
                for (int c = 0; c < NC / 4; c++) {
                    float4 w = wr[c];
                    acc[4 * c + 0] += xv * w.x;
                    acc[4 * c + 1] += xv * w.y;
                    acc[4 * c + 2] += xv * w.z;
                    acc[4 * c + 3] += xv * w.w;
                }
            }
        }
        __syncthreads();
    }
    if (valid) {
        float d = g_dis[row];
        float* ho = g_h + (size_t)row * N + cg * NC;
#pragma unroll
        for (int c = 0; c < NC / 4; c++) {
            *reinterpret_cast<float4*>(ho + 4 * c) =
                make_float4(acc[4 * c] * d, acc[4 * c + 1] * d,
                            acc[4 * c + 2] * d, acc[4 * c + 3] * d);
        }
    }
}

// ---------------- CSR aggregation ----------------
// out[n] = dis[n]*(h[n] + sum_{e->n} h[src_e]) + b
// FINAL=false: writes g_acc (device symbol, referenced internally), float4.
// FINAL=true : writes `out` (harness pointer, only 4B aligned), scalar stores.
template <int N, bool FINAL>
__global__ __launch_bounds__(256) void k_agg(const float* __restrict__ b,
                                             float* __restrict__ out) {
    constexpr int VE = N / 32;  // 4 (N=128) or 2 (N=64)
    const int lane = threadIdx.x & 31;
    const int warp = threadIdx.x >> 5;
    float bv[VE];
#pragma unroll
    for (int i = 0; i < VE; i++) bv[i] = b[lane * VE + i];

    for (int node = blockIdx.x * 8 + warp; node < NN; node += gridDim.x * 8) {
        float acc[VE];
        {
            const float* hr = g_h + (size_t)node * N + lane * VE;
            if constexpr (VE == 4) {
                float4 t = *(const float4*)hr;
                acc[0] = t.x; acc[1] = t.y; acc[2] = t.z; acc[3] = t.w;
            } else {
                float2 t = *(const float2*)hr;
                acc[0] = t.x; acc[1] = t.y;
            }
        }
        int beg = g_rows[node], end = g_rows[node + 1];
        int e = beg;
        for (; e + 1 < end; e += 2) {  // 2-edge unroll for MLP
            int s0 = g_csrc[e], s1 = g_csrc[e + 1];
            const float* v0 = g_h + (size_t)s0 * N + lane * VE;
            const float* v1 = g_h + (size_t)s1 * N + lane * VE;
            if constexpr (VE == 4) {
                float4 a = *(const float4*)v0;
                float4 c = *(const float4*)v1;
                acc[0] += a.x + c.x; acc[1] += a.y + c.y;
                acc[2] += a.z + c.z; acc[3] += a.w + c.w;
            } else {
                float2 a = *(const float2*)v0;
                float2 c = *(const float2*)v1;
                acc[0] += a.x + c.x; acc[1] += a.y + c.y;
            }
        }
        if (e < end) {
            int s0 = g_csrc[e];
            const float* v0 = g_h + (size_t)s0 * N + lane * VE;
            if constexpr (VE == 4) {
                float4 a = *(const float4*)v0;
                acc[0] += a.x; acc[1] += a.y; acc[2] += a.z; acc[3] += a.w;
            } else {
                float2 a = *(const float2*)v0;
                acc[0] += a.x; acc[1] += a.y;
            }
        }
        float dd = g_dis[node];
        float v[VE];
#pragma unroll
        for (int i = 0; i < VE; i++) v[i] = fmaf(acc[i], dd, bv[i]);

        if constexpr (FINAL) {
            float* orow = out + (size_t)node * N + lane * VE;
#pragma unroll
            for (int i = 0; i < VE; i++) orow[i] = v[i];
        } else {
            float* orow = g_acc + (size_t)node * N + lane * VE;
            *(float4*)orow = make_float4(v[0], v[1], v[2], v[3]);
        }
    }
}

// ---------------- BN column stats over g_acc (R1-proven structure) ----------------
__global__ __launch_bounds__(256) void k_stats() {
    __shared__ float ssum[256], ssq[256];
    int tid = threadIdx.x;
    int col = tid & 127;
    int rh = tid >> 7;
    int row0 = blockIdx.x * 32;
    float sum = 0.f, sq = 0.f;
    int rend = min(row0 + 32, NN);
    for (int r = row0 + rh; r < rend; r += 2) {
        float v = g_acc[(size_t)r * 128 + col];
        sum += v;
        sq += v * v;
    }
    ssum[tid] = sum;
    ssq[tid] = sq;
    __syncthreads();
    if (tid < 128) {
        atomicAdd(&g_stats[col], ssum[tid] + ssum[tid + 128]);
        atomicAdd(&g_stats[128 + col], ssq[tid] + ssq[tid + 128]);
    }
}

// ---------------- BN prep + apply ----------------
__global__ void k_bnprep(const float* __restrict__ g, const float* __restrict__ beta) {
    int c = threadIdx.x;  // 128 threads
    float m = g_stats[c] * (1.f / NN);
    float var = g_stats[128 + c] * (1.f / NN) - m * m;
    float sc = g[c] * rsqrtf(var + 1e-5f);
    g_stats[256 + c] = sc;
    g_stats[384 + c] = beta[c] - m * sc;
}

__global__ __launch_bounds__(256) void k_bnapply() {
    int row = blockIdx.x * 8 + (threadIdx.x >> 5);
    int lane = threadIdx.x & 31;
    if (row >= NN) return;
    float4 v = *reinterpret_cast<const float4*>(g_acc + (size_t)row * 128 + lane * 4);
    float4 sc = *reinterpret_cast<const float4*>(g_stats + 256 + lane * 4);
    float4 sh = *reinterpret_cast<const float4*>(g_stats + 384 + lane * 4);
    float y0 = fmaxf(fmaf(v.x, sc.x, sh.x), 0.f);
    float y1 = fmaxf(fmaf(v.y, sc.y, sh.y), 0.f);
    float y2 = fmaxf(fmaf(v.z, sc.z, sh.z), 0.f);
    float y3 = fmaxf(fmaf(v.w, sc.w, sh.w), 0.f);
    float sq = y0 * y0 + y1 * y1 + y2 * y2 + y3 * y3;
#pragma unroll
    for (int o = 16; o; o >>= 1) sq += __shfl_xor_sync(0xffffffffu, sq, o);
    float inv = 1.f / fmaxf(sqrtf(sq), 1e-12f);
    *reinterpret_cast<float4*>(g_x + (size_t)row * 128 + lane * 4) =
        make_float4(y0 * inv, y1 * inv, y2 * inv, y3 * inv);
}

// ---------------- BPR loss ----------------
__global__ __launch_bounds__(256) void k_loss(const float* __restrict__ xo,
                                              const int* __restrict__ uid,
                                              const int* __restrict__ pid,
                                              const int* __restrict__ nid) {
    int s = blockIdx.x * 8 + (threadIdx.x >> 5);
    int lane = threadIdx.x & 31;
    if (s >= NBATCH) return;
    const float* u = xo + (size_t)uid[s] * 64;
    const float* p = xo + (size_t)(USER_NUM + pid[s]) * 64;
    const float* nr = xo + (size_t)(USER_NUM + nid[s]) * 64;
    float ps = 0.f, ns = 0.f;
#pragma unroll
    for (int j = 0; j < 2; j++) {
        int c = lane + j * 32;
        float uv = u[c];
        ps += uv * p[c];
        ns += uv * nr[c];
    }
#pragma unroll
    for (int o = 16; o; o >>= 1) {
        ps += __shfl_xor_sync(0xffffffffu, ps, o);
        ns += __shfl_xor_sync(0xffffffffu, ns, o);
    }
    if (lane == 0) {
        float z = ps - ns;
        float ls = fminf(z, 0.f) - log1pf(expf(-fabsf(z)));
        atomicAdd(&g_loss, ls);
    }
}

__global__ void k_wloss(float* __restrict__ out) {
    out[0] = -g_loss * (1.f / NBATCH);
}

// ---------------- launch ----------------
extern "C" void kernel_launch(void* const* d_in, const int* in_sizes, int n_in,
                              void* d_out, int out_size) {
    const float* user_emb = (const float*)d_in[0];
    const float* item_emb = (const float*)d_in[1];
    const float* W0 = (const float*)d_in[2];
    const float* b0 = (const float*)d_in[3];
    const float* g0 = (const float*)d_in[4];
    const float* beta0 = (const float*)d_in[5];
    const float* W1 = (const float*)d_in[6];
    const float* b1 = (const float*)d_in[7];
    const float* g1 = (const float*)d_in[8];
    const float* beta1 = (const float*)d_in[9];
    const float* W2 = (const float*)d_in[10];
    const float* b2 = (const float*)d_in[11];
    const int* user_id = (const int*)d_in[12];
    const int* pos_item = (const int*)d_in[13];
    const int* neg_item = (const int*)d_in[14];
    const int* ei = (const int*)d_in[15];
    const int* src = ei;
    const int* dst = ei + NE;

    float* out = (float*)d_out;
    float* xout = out + 1;  // [rec_loss, x(150000x64)] -- only 4B aligned!

    const int EB = (NE + 255) / 256;
    const int AGGB = 2048;
    const int SB = (NN + 31) / 32;

    // setup + CSR build
    k_zero<<<(NN + 255) / 256, 256>>>();
    k_deg<<<EB, 256>>>(dst);
    k_dis<<<(NN + 255) / 256, 256>>>();
    k_concat<<<(NN * 64 + 255) / 256, 256>>>(user_emb, item_emb);
    k_scan1<<<SCAN_B, 256>>>();
    k_scan2<<<1, 1024>>>();
    k_scan3<<<SCAN_B + 1, 256>>>();
    k_csrfill<<<EB, 256>>>(src, dst);

    const int GB = (NN + 63) / 64;

    // ---- layer 0: 64 -> 128 ----
    k_gemm<64, 128><<<GB, 256>>>(W0);
    k_agg<128, false><<<AGGB, 256>>>(b0, nullptr);
    k_stats<<<SB, 256>>>();
    k_bnprep<<<1, 128>>>(g0, beta0);
    k_bnapply<<<(NN + 7) / 8, 256>>>();

    // ---- layer 1: 128 -> 128 ----
    k_zstats<<<1, 256>>>();
    k_gemm<128, 128><<<GB, 256>>>(W1);
    k_agg<128, false><<<AGGB, 256>>>(b1, nullptr);
    k_stats<<<SB, 256>>>();
    k_bnprep<<<1, 128>>>(g1, beta1);
    k_bnapply<<<(NN + 7) / 8, 256>>>();

    // ---- layer 2: 128 -> 64 ----
    k_gemm<128, 64><<<GB, 256>>>(W2);
    k_agg<64, true><<<AGGB, 256>>>(b2, xout);

    // ---- loss ----
    k_loss<<<(NBATCH + 7) / 8, 256>>>(xout, user_id, pos_item, neg_item);
    k_wloss<<<1, 1>>>(out);
}

// round 6
// speedup vs baseline: 1.3073x; 1.0460x over previous
#include <cuda_runtime.h>
#include <cuda_bf16.h>
#include <cuda_fp16.h>
#include <math.h>

#define USER_NUM 100000
#define ITEM_NUM 50000
#define NN 150000
#define NE 2400000
#define NBATCH 4096
#define SCAN_B ((NN + 255) / 256)   // 586

// Scratch (device globals; allocation is forbidden).
// Device symbols are referenced ONLY inside kernels (never as host-side args).
__device__ float g_x[150016 * 128];        // current features (fp32)
__device__ uint4 g_h16raw[150016 * 128 / 8];  // hs = (x@W)*dis[row], fp16, 16B-aligned
#define G_H16 (reinterpret_cast<__half*>(g_h16raw))
__device__ float g_acc[150016 * 128];      // conv output (pre-BN, fp32)
__device__ float g_dis[150016];            // rsqrt(1+deg)
__device__ int   g_degi[150016];
__device__ int   g_rows[150016 + 16];      // CSR row offsets (by dst)
__device__ int   g_cursor[150016];
__device__ int   g_part[1024];
__device__ int   g_csrc[NE];               // CSR column (src) ids
__device__ float g_stats[512];             // colsum | colsq | scale | shift
__device__ float g_loss;

// ---------------- setup ----------------

__global__ void k_zero() {
    int i = blockIdx.x * 256 + threadIdx.x;
    if (i < NN) g_degi[i] = 0;
    if (i < 256) g_stats[i] = 0.f;
    if (i == 0) g_loss = 0.f;
}

__global__ void k_zstats() { g_stats[threadIdx.x] = 0.f; }  // 256 threads

__global__ void k_deg(const int* __restrict__ dst) {
    int e = blockIdx.x * 256 + threadIdx.x;
    if (e < NE) atomicAdd(&g_degi[dst[e]], 1);
}

__global__ void k_dis() {
    int i = blockIdx.x * 256 + threadIdx.x;
    if (i < NN) g_dis[i] = rsqrtf(1.f + (float)g_degi[i]);
}

// vectorized concat: both sources are 16B-aligned, element counts divisible by 4
__global__ void k_concat(const float* __restrict__ ue, const float* __restrict__ ie) {
    int i = blockIdx.x * 256 + threadIdx.x;  // float4 index
    const int UT = USER_NUM * 16;            // user float4 count
    const int TT = NN * 16;
    if (i < TT) {
        float4 v = (i < UT) ? ((const float4*)ue)[i] : ((const float4*)ie)[i - UT];
        ((float4*)g_x)[i] = v;
    }
}

// ---------------- prefix scan (3 kernels) ----------------

__global__ void k_scan1() {
    __shared__ int s[256];
    int tid = threadIdx.x;
    int i = blockIdx.x * 256 + tid;
    int v = (i < NN) ? g_degi[i] : 0;
    s[tid] = v;
    __syncthreads();
    for (int off = 1; off < 256; off <<= 1) {
        int t = (tid >= off) ? s[tid - off] : 0;
        __syncthreads();
        s[tid] += t;
        __syncthreads();
    }
    if (i < NN) g_rows[i] = s[tid] - v;
    if (tid == 255) g_part[blockIdx.x] = s[255];
}

__global__ void k_scan2() {  // 1 block, 1024 threads
    __shared__ int s[1024];
    int tid = threadIdx.x;
    int v = (tid < SCAN_B) ? g_part[tid] : 0;
    s[tid] = v;
    __syncthreads();
    for (int off = 1; off < 1024; off <<= 1) {
        int t = (tid >= off) ? s[tid - off] : 0;
        __syncthreads();
        s[tid] += t;
        __syncthreads();
    }
    if (tid < SCAN_B) g_part[tid] = s[tid] - v;
}

__global__ void k_scan3() {
    int i = blockIdx.x * 256 + threadIdx.x;
    if (i < NN) {
        int r = g_rows[i] + g_part[i >> 8];
        g_rows[i] = r;
        g_cursor[i] = r;
    }
    if (i == NN) g_rows[NN] = NE;
}

__global__ void k_csrfill(const int* __restrict__ src, const int* __restrict__ dst) {
    int e = blockIdx.x * 256 + threadIdx.x;
    if (e < NE) {
        int d = dst[e];
        int p = atomicAdd(&g_cursor[d], 1);
        g_csrc[p] = src[e];
    }
}

// ---------------- GEMM: g_h16 = fp16( (g_x @ W) * dis[row] ) ----------------
template <int K, int N>
__global__ __launch_bounds__(256) void k_gemm(const float* __restrict__ W) {
    __shared__ float Ws[64 * N];
    const int tid = threadIdx.x;
    const int row = blockIdx.x * 64 + (tid >> 2);
    const int cg = tid & 3;
    constexpr int NC = N / 4;
    float acc[NC];
#pragma unroll
    for (int c = 0; c < NC; c++) acc[c] = 0.f;
    const bool valid = row < NN;

    for (int kc = 0; kc < K; kc += 64) {
#pragma unroll
        for (int i = 0; i < (64 * N) / 256; i++) {
            int idx = tid + i * 256;
            Ws[idx] = W[kc * N + idx];
        }
        __syncthreads();
        if (valid) {
            const float* xr = g_x + (size_t)row * K + kc;
#pragma unroll 8
            for (int k = 0; k < 64; k++) {
                float xv = xr[k];
                const float4* wr = reinterpret_cast<const float4*>(Ws + k * N + cg * NC);
#pragma unroll
                for (int c = 0; c < NC / 4; c++) {
                    float4 w = wr[c];
                    acc[4 * c + 0] += xv * w.x;
                    acc[4 * c + 1] += xv * w.y;
                    acc[4 * c + 2] += xv * w.z;
                    acc[4 * c + 3] += xv * w.w;
                }
            }
        }
        __syncthreads();
    }
    if (valid) {
        float d = g_dis[row];
        __align__(16) __half2 hbuf[NC / 2];
#pragma unroll
        for (int c = 0; c < NC / 2; c++)
            hbuf[c] = __floats2half2_rn(acc[2 * c] * d, acc[2 * c + 1] * d);
        uint4* ho = reinterpret_cast<uint4*>(G_H16 + (size_t)row * N + cg * NC);
        const uint4* hb = reinterpret_cast<const uint4*>(hbuf);
#pragma unroll
        for (int i = 0; i < NC / 8; i++) ho[i] = hb[i];
    }
}

// ---------------- CSR aggregation ----------------
// out[n] = dis[n]*(h[n] + sum_{e->n} h[src_e]) + b, h read as fp16, accum fp32.
// FINAL=false: writes g_acc (internal symbol) with float4.
// FINAL=true : writes harness `out` (4B-aligned) with scalar stores.
template <int N, bool FINAL>
__global__ __launch_bounds__(256) void k_agg(const float* __restrict__ b,
                                             float* __restrict__ out) {
    constexpr int VE = N / 32;  // 4 (N=128) or 2 (N=64)
    const int lane = threadIdx.x & 31;
    const int warp = threadIdx.x >> 5;
    float bv[VE];
#pragma unroll
    for (int i = 0; i < VE; i++) bv[i] = b[lane * VE + i];

    for (int node = blockIdx.x * 8 + warp; node < NN; node += gridDim.x * 8) {
        float acc[VE];
        // self row
        if constexpr (VE == 4) {
            uint2 raw = *(const uint2*)(G_H16 + (size_t)node * N + lane * 4);
            float2 f0 = __half22float2(*reinterpret_cast<__half2*>(&raw.x));
            float2 f1 = __half22float2(*reinterpret_cast<__half2*>(&raw.y));
            acc[0] = f0.x; acc[1] = f0.y; acc[2] = f1.x; acc[3] = f1.y;
        } else {
            unsigned raw = *(const unsigned*)(G_H16 + (size_t)node * N + lane * 2);
            float2 f = __half22float2(*reinterpret_cast<__half2*>(&raw));
            acc[0] = f.x; acc[1] = f.y;
        }
        int beg = g_rows[node], end = g_rows[node + 1];
        int e = beg;
        for (; e + 1 < end; e += 2) {  // 2-edge unroll for MLP
            int s0 = g_csrc[e], s1 = g_csrc[e + 1];
            if constexpr (VE == 4) {
                uint2 r0 = *(const uint2*)(G_H16 + (size_t)s0 * N + lane * 4);
                uint2 r1 = *(const uint2*)(G_H16 + (size_t)s1 * N + lane * 4);
                float2 a0 = __half22float2(*reinterpret_cast<__half2*>(&r0.x));
                float2 a1 = __half22float2(*reinterpret_cast<__half2*>(&r0.y));
                float2 c0 = __half22float2(*reinterpret_cast<__half2*>(&r1.x));
                float2 c1 = __half22float2(*reinterpret_cast<__half2*>(&r1.y));
                acc[0] += a0.x + c0.x; acc[1] += a0.y + c0.y;
                acc[2] += a1.x + c1.x; acc[3] += a1.y + c1.y;
            } else {
                unsigned r0 = *(const unsigned*)(G_H16 + (size_t)s0 * N + lane * 2);
                unsigned r1 = *(const unsigned*)(G_H16 + (size_t)s1 * N + lane * 2);
                float2 a = __half22float2(*reinterpret_cast<__half2*>(&r0));
                float2 c = __half22float2(*reinterpret_cast<__half2*>(&r1));
                acc[0] += a.x + c.x; acc[1] += a.y + c.y;
            }
        }
        if (e < end) {
            int s0 = g_csrc[e];
            if constexpr (VE == 4) {
                uint2 r0 = *(const uint2*)(G_H16 + (size_t)s0 * N + lane * 4);
                float2 a0 = __half22float2(*reinterpret_cast<__half2*>(&r0.x));
                float2 a1 = __half22float2(*reinterpret_cast<__half2*>(&r0.y));
                acc[0] += a0.x; acc[1] += a0.y; acc[2] += a1.x; acc[3] += a1.y;
            } else {
                unsigned r0 = *(const unsigned*)(G_H16 + (size_t)s0 * N + lane * 2);
                float2 a = __half22float2(*reinterpret_cast<__half2*>(&r0));
                acc[0] += a.x; acc[1] += a.y;
            }
        }
        float dd = g_dis[node];
        float v[VE];
#pragma unroll
        for (int i = 0; i < VE; i++) v[i] = fmaf(acc[i], dd, bv[i]);

        if constexpr (FINAL) {
            float* orow = out + (size_t)node * N + lane * VE;
#pragma unroll
            for (int i = 0; i < VE; i++) orow[i] = v[i];
        } else {
            float* orow = g_acc + (size_t)node * N + lane * VE;
            *(float4*)orow = make_float4(v[0], v[1], v[2], v[3]);
        }
    }
}

// ---------------- BN column stats over g_acc ----------------
__global__ __launch_bounds__(256) void k_stats() {
    __shared__ float ssum[256], ssq[256];
    int tid = threadIdx.x;
    int col = tid & 127;
    int rh = tid >> 7;
    int row0 = blockIdx.x * 32;
    float sum = 0.f, sq = 0.f;
    int rend = min(row0 + 32, NN);
    for (int r = row0 + rh; r < rend; r += 2) {
        float v = g_acc[(size_t)r * 128 + col];
        sum += v;
        sq += v * v;
    }
    ssum[tid] = sum;
    ssq[tid] = sq;
    __syncthreads();
    if (tid < 128) {
        atomicAdd(&g_stats[col], ssum[tid] + ssum[tid + 128]);
        atomicAdd(&g_stats[128 + col], ssq[tid] + ssq[tid + 128]);
    }
}

// ---------------- BN prep + apply ----------------
__global__ void k_bnprep(const float* __restrict__ g, const float* __restrict__ beta) {
    int c = threadIdx.x;  // 128 threads
    float m = g_stats[c] * (1.f / NN);
    float var = g_stats[128 + c] * (1.f / NN) - m * m;
    float sc = g[c] * rsqrtf(var + 1e-5f);
    g_stats[256 + c] = sc;
    g_stats[384 + c] = beta[c] - m * sc;
}

__global__ __launch_bounds__(256) void k_bnapply() {
    int row = blockIdx.x * 8 + (threadIdx.x >> 5);
    int lane = threadIdx.x & 31;
    if (row >= NN) return;
    float4 v = *reinterpret_cast<const float4*>(g_acc + (size_t)row * 128 + lane * 4);
    float4 sc = *reinterpret_cast<const float4*>(g_stats + 256 + lane * 4);
    float4 sh = *reinterpret_cast<const float4*>(g_stats + 384 + lane * 4);
    float y0 = fmaxf(fmaf(v.x, sc.x, sh.x), 0.f);
    float y1 = fmaxf(fmaf(v.y, sc.y, sh.y), 0.f);
    float y2 = fmaxf(fmaf(v.z, sc.z, sh.z), 0.f);
    float y3 = fmaxf(fmaf(v.w, sc.w, sh.w), 0.f);
    float sq = y0 * y0 + y1 * y1 + y2 * y2 + y3 * y3;
#pragma unroll
    for (int o = 16; o; o >>= 1) sq += __shfl_xor_sync(0xffffffffu, sq, o);
    float inv = 1.f / fmaxf(sqrtf(sq), 1e-12f);
    *reinterpret_cast<float4*>(g_x + (size_t)row * 128 + lane * 4) =
        make_float4(y0 * inv, y1 * inv, y2 * inv, y3 * inv);
}

// ---------------- BPR loss ----------------
__global__ __launch_bounds__(256) void k_loss(const float* __restrict__ xo,
                                              const int* __restrict__ uid,
                                              const int* __restrict__ pid,
                                              const int* __restrict__ nid) {
    int s = blockIdx.x * 8 + (threadIdx.x >> 5);
    int lane = threadIdx.x & 31;
    if (s >= NBATCH) return;
    const float* u = xo + (size_t)uid[s] * 64;
    const float* p = xo + (size_t)(USER_NUM + pid[s]) * 64;
    const float* nr = xo + (size_t)(USER_NUM + nid[s]) * 64;
    float ps = 0.f, ns = 0.f;
#pragma unroll
    for (int j = 0; j < 2; j++) {
        int c = lane + j * 32;
        float uv = u[c];
        ps += uv * p[c];
        ns += uv * nr[c];
    }
#pragma unroll
    for (int o = 16; o; o >>= 1) {
        ps += __shfl_xor_sync(0xffffffffu, ps, o);
        ns += __shfl_xor_sync(0xffffffffu, ns, o);
    }
    if (lane == 0) {
        float z = ps - ns;
        float ls = fminf(z, 0.f) - log1pf(expf(-fabsf(z)));
        atomicAdd(&g_loss, ls);
    }
}

__global__ void k_wloss(float* __restrict__ out) {
    out[0] = -g_loss * (1.f / NBATCH);
}

// ---------------- launch ----------------
extern "C" void kernel_launch(void* const* d_in, const int* in_sizes, int n_in,
                              void* d_out, int out_size) {
    const float* user_emb = (const float*)d_in[0];
    const float* item_emb = (const float*)d_in[1];
    const float* W0 = (const float*)d_in[2];
    const float* b0 = (const float*)d_in[3];
    const float* g0 = (const float*)d_in[4];
    const float* beta0 = (const float*)d_in[5];
    const float* W1 = (const float*)d_in[6];
    const float* b1 = (const float*)d_in[7];
    const float* g1 = (const float*)d_in[8];
    const float* beta1 = (const float*)d_in[9];
    const float* W2 = (const float*)d_in[10];
    const float* b2 = (const float*)d_in[11];
    const int* user_id = (const int*)d_in[12];
    const int* pos_item = (const int*)d_in[13];
    const int* neg_item = (const int*)d_in[14];
    const int* ei = (const int*)d_in[15];
    const int* src = ei;
    const int* dst = ei + NE;

    float* out = (float*)d_out;
    float* xout = out + 1;  // [rec_loss, x(150000x64)] -- only 4B aligned!

    const int EB = (NE + 255) / 256;
    const int AGGB = 2048;
    const int SB = (NN + 31) / 32;

    // setup + CSR build
    k_zero<<<(NN + 255) / 256, 256>>>();
    k_deg<<<EB, 256>>>(dst);
    k_dis<<<(NN + 255) / 256, 256>>>();
    k_concat<<<(NN * 16 + 255) / 256, 256>>>(user_emb, item_emb);
    k_scan1<<<SCAN_B, 256>>>();
    k_scan2<<<1, 1024>>>();
    k_scan3<<<SCAN_B + 1, 256>>>();
    k_csrfill<<<EB, 256>>>(src, dst);

    const int GB = (NN + 63) / 64;

    // ---- layer 0: 64 -> 128 ----
    k_gemm<64, 128><<<GB, 256>>>(W0);
    k_agg<128, false><<<AGGB, 256>>>(b0, nullptr);
    k_stats<<<SB, 256>>>();
    k_bnprep<<<1, 128>>>(g0, beta0);
    k_bnapply<<<(NN + 7) / 8, 256>>>();

    // ---- layer 1: 128 -> 128 ----
    k_zstats<<<1, 256>>>();
    k_gemm<128, 128><<<GB, 256>>>(W1);
    k_agg<128, false><<<AGGB, 256>>>(b1, nullptr);
    k_stats<<<SB, 256>>>();
    k_bnprep<<<1, 128>>>(g1, beta1);
    k_bnapply<<<(NN + 7) / 8, 256>>>();

    // ---- layer 2: 128 -> 64 ----
    k_gemm<128, 64><<<GB, 256>>>(W2);
    k_agg<64, true><<<AGGB, 256>>>(b2, xout);

    // ---- loss ----
    k_loss<<<(NBATCH + 7) / 8, 256>>>(xout, user_id, pos_item, neg_item);
    k_wloss<<<1, 1>>>(out);
}

// round 7
// speedup vs baseline: 4.4589x; 3.4108x over previous
#include <cuda_runtime.h>
#include <cuda_bf16.h>
#include <cuda_fp16.h>
#include <math.h>

#define USER_NUM 100000
#define ITEM_NUM 50000
#define NN 150000
#define NE 2400000
#define NBATCH 4096
#define SCAN_B ((NN + 255) / 256)   // 586

// Scratch (device globals; allocation is forbidden).
// Device symbols are referenced ONLY inside kernels (never as host-side args).
__device__ float g_x[150016 * 128];           // current features (fp32)
__device__ uint4 g_h16raw[150016 * 128 / 8];  // hs = (x@W)*dis[row], fp16
#define G_H16 (reinterpret_cast<__half*>(g_h16raw))
__device__ float g_acc[150016 * 128];         // conv output (pre-BN, fp32)
__device__ float g_dis[150016];               // rsqrt(1+deg)
__device__ int   g_degi[150016];
__device__ int   g_rows[150016 + 16];         // CSR row offsets (by dst)
__device__ int   g_cursor[150016];
__device__ int   g_part[1024];
__device__ int   g_csrc[NE];                  // CSR column (src) ids
__device__ float g_stats[512];                // colsum | colsq | scale | shift
__device__ float g_loss;

// ---------------- setup ----------------

__global__ void k_zero() {
    int i = blockIdx.x * 256 + threadIdx.x;
    if (i < NN) g_degi[i] = 0;
    if (i < 256) g_stats[i] = 0.f;
    if (i == 0) g_loss = 0.f;
}

__global__ void k_zstats() { g_stats[threadIdx.x] = 0.f; }  // 256 threads

__global__ void k_deg(const int* __restrict__ dst) {
    int e = blockIdx.x * 256 + threadIdx.x;
    if (e < NE) atomicAdd(&g_degi[dst[e]], 1);
}

__global__ void k_dis() {
    int i = blockIdx.x * 256 + threadIdx.x;
    if (i < NN) g_dis[i] = rsqrtf(1.f + (float)g_degi[i]);
}

__global__ void k_concat(const float* __restrict__ ue, const float* __restrict__ ie) {
    int i = blockIdx.x * 256 + threadIdx.x;  // float4 index
    const int UT = USER_NUM * 16;
    const int TT = NN * 16;
    if (i < TT) {
        float4 v = (i < UT) ? ((const float4*)ue)[i] : ((const float4*)ie)[i - UT];
        ((float4*)g_x)[i] = v;
    }
}

// ---------------- prefix scan ----------------

__global__ void k_scan1() {
    __shared__ int s[256];
    int tid = threadIdx.x;
    int i = blockIdx.x * 256 + tid;
    int v = (i < NN) ? g_degi[i] : 0;
    s[tid] = v;
    __syncthreads();
    for (int off = 1; off < 256; off <<= 1) {
        int t = (tid >= off) ? s[tid - off] : 0;
        __syncthreads();
        s[tid] += t;
        __syncthreads();
    }
    if (i < NN) g_rows[i] = s[tid] - v;
    if (tid == 255) g_part[blockIdx.x] = s[255];
}

__global__ void k_scan2() {  // 1 block, 1024 threads
    __shared__ int s[1024];
    int tid = threadIdx.x;
    int v = (tid < SCAN_B) ? g_part[tid] : 0;
    s[tid] = v;
    __syncthreads();
    for (int off = 1; off < 1024; off <<= 1) {
        int t = (tid >= off) ? s[tid - off] : 0;
        __syncthreads();
        s[tid] += t;
        __syncthreads();
    }
    if (tid < SCAN_B) g_part[tid] = s[tid] - v;
}

__global__ void k_scan3() {
    int i = blockIdx.x * 256 + threadIdx.x;
    if (i < NN) {
        int r = g_rows[i] + g_part[i >> 8];
        g_rows[i] = r;
        g_cursor[i] = r;
    }
    if (i == NN) g_rows[NN] = NE;
}

__global__ void k_csrfill(const int* __restrict__ src, const int* __restrict__ dst) {
    int e = blockIdx.x * 256 + threadIdx.x;
    if (e < NE) {
        int d = dst[e];
        int p = atomicAdd(&g_cursor[d], 1);
        g_csrc[p] = src[e];
    }
}

// ---------------- register-blocked GEMM ----------------
// g_h16[r][n] = fp16( (g_x[r] @ W)[n] * dis[r] )
// Tile: 128 rows x N cols per block, 256 threads, micro-tile TM x 8 per thread.
template <int K, int N, int TM>
__global__ __launch_bounds__(256) void k_gemm2(const float* __restrict__ W) {
    constexpr int KB = 32;
    constexpr int CT = N / 8;     // threads along cols
    static_assert(256 % CT == 0 && (256 / CT) * TM == 128, "layout");
    __shared__ float As[KB][132];  // transposed A tile (pad to vary banks per k)
    __shared__ float Bs[KB][N];

    const int tid = threadIdx.x;
    const int tx = tid % CT;
    const int ty = tid / CT;
    const int row0 = blockIdx.x * 128;

    float acc[TM][8];
#pragma unroll
    for (int i = 0; i < TM; i++)
#pragma unroll
        for (int j = 0; j < 8; j++) acc[i][j] = 0.f;

    for (int kc = 0; kc < K; kc += KB) {
        // stage A: 128 rows x 32 k, transposed. 2 threads per row, 16 floats each.
        {
            int r = tid >> 1;
            int kq = (tid & 1) * 16;
            int rr = row0 + r; if (rr >= NN) rr = NN - 1;
            const float* srcp = g_x + (size_t)rr * K + kc + kq;
            float4 v0 = *(const float4*)(srcp);
            float4 v1 = *(const float4*)(srcp + 4);
            float4 v2 = *(const float4*)(srcp + 8);
            float4 v3 = *(const float4*)(srcp + 12);
            As[kq + 0][r] = v0.x;  As[kq + 1][r] = v0.y;
            As[kq + 2][r] = v0.z;  As[kq + 3][r] = v0.w;
            As[kq + 4][r] = v1.x;  As[kq + 5][r] = v1.y;
            As[kq + 6][r] = v1.z;  As[kq + 7][r] = v1.w;
            As[kq + 8][r] = v2.x;  As[kq + 9][r] = v2.y;
            As[kq +10][r] = v2.z;  As[kq +11][r] = v2.w;
            As[kq +12][r] = v3.x;  As[kq +13][r] = v3.y;
            As[kq +14][r] = v3.z;  As[kq +15][r] = v3.w;
        }
        // stage B: rows kc..kc+31 of W are contiguous
        {
            const float4* wsrc = (const float4*)(W + (size_t)kc * N);
#pragma unroll
            for (int i = 0; i < (KB * N / 4) / 256; i++)
                ((float4*)&Bs[0][0])[tid + i * 256] = wsrc[tid + i * 256];
        }
        __syncthreads();

#pragma unroll
        for (int k = 0; k < KB; k++) {
            float b[8];
            *(float4*)(b)     = *(const float4*)&Bs[k][tx * 8];
            *(float4*)(b + 4) = *(const float4*)&Bs[k][tx * 8 + 4];
            float a[TM];
#pragma unroll
            for (int i = 0; i < TM; i++) a[i] = As[k][ty * TM + i];
#pragma unroll
            for (int i = 0; i < TM; i++)
#pragma unroll
                for (int j = 0; j < 8; j++) acc[i][j] = fmaf(a[i], b[j], acc[i][j]);
        }
        __syncthreads();
    }

    // epilogue: scale by dis, convert fp16, store 16B per row-slice
#pragma unroll
    for (int i = 0; i < TM; i++) {
        int r = row0 + ty * TM + i;
        if (r < NN) {
            float d = g_dis[r];
            __align__(16) __half2 h[4];
#pragma unroll
            for (int j = 0; j < 4; j++)
                h[j] = __floats2half2_rn(acc[i][2 * j] * d, acc[i][2 * j + 1] * d);
            *reinterpret_cast<uint4*>(G_H16 + (size_t)r * N + tx * 8) =
                *reinterpret_cast<const uint4*>(h);
        }
    }
}

// ---------------- CSR aggregation (4-edge unroll) ----------------
// out[n] = dis[n]*(h[n] + sum_{e->n} h[src_e]) + b; h fp16, accum fp32.
template <int N, bool FINAL>
__global__ __launch_bounds__(256) void k_agg(const float* __restrict__ b,
                                             float* __restrict__ out) {
    constexpr int VE = N / 32;  // 4 or 2
    const int lane = threadIdx.x & 31;
    const int warp = threadIdx.x >> 5;
    float bv[VE];
#pragma unroll
    for (int i = 0; i < VE; i++) bv[i] = b[lane * VE + i];

    for (int node = blockIdx.x * 8 + warp; node < NN; node += gridDim.x * 8) {
        float acc[VE];
        if constexpr (VE == 4) {
            uint2 raw = *(const uint2*)(G_H16 + (size_t)node * N + lane * 4);
            float2 f0 = __half22float2(*reinterpret_cast<__half2*>(&raw.x));
            float2 f1 = __half22float2(*reinterpret_cast<__half2*>(&raw.y));
            acc[0] = f0.x; acc[1] = f0.y; acc[2] = f1.x; acc[3] = f1.y;
        } else {
            unsigned raw = *(const unsigned*)(G_H16 + (size_t)node * N + lane * 2);
            float2 f = __half22float2(*reinterpret_cast<__half2*>(&raw));
            acc[0] = f.x; acc[1] = f.y;
        }
        int beg = g_rows[node], end = g_rows[node + 1];
        int e = beg;
        for (; e + 3 < end; e += 4) {  // 4 independent gathers -> MLP=4
            int s0 = g_csrc[e], s1 = g_csrc[e + 1], s2 = g_csrc[e + 2], s3 = g_csrc[e + 3];
            if constexpr (VE == 4) {
                uint2 r0 = *(const uint2*)(G_H16 + (size_t)s0 * N + lane * 4);
                uint2 r1 = *(const uint2*)(G_H16 + (size_t)s1 * N + lane * 4);
                uint2 r2 = *(const uint2*)(G_H16 + (size_t)s2 * N + lane * 4);
                uint2 r3 = *(const uint2*)(G_H16 + (size_t)s3 * N + lane * 4);
                float2 a0 = __half22float2(*reinterpret_cast<__half2*>(&r0.x));
                float2 a1 = __half22float2(*reinterpret_cast<__half2*>(&r0.y));
                float2 b0_ = __half22float2(*reinterpret_cast<__half2*>(&r1.x));
                float2 b1_ = __half22float2(*reinterpret_cast<__half2*>(&r1.y));
                float2 c0 = __half22float2(*reinterpret_cast<__half2*>(&r2.x));
                float2 c1 = __half22float2(*reinterpret_cast<__half2*>(&r2.y));
                float2 d0 = __half22float2(*reinterpret_cast<__half2*>(&r3.x));
                float2 d1 = __half22float2(*reinterpret_cast<__half2*>(&r3.y));
                acc[0] += (a0.x + b0_.x) + (c0.x + d0.x);
                acc[1] += (a0.y + b0_.y) + (c0.y + d0.y);
                acc[2] += (a1.x + b1_.x) + (c1.x + d1.x);
                acc[3] += (a1.y + b1_.y) + (c1.y + d1.y);
            } else {
                unsigned r0 = *(const unsigned*)(G_H16 + (size_t)s0 * N + lane * 2);
                unsigned r1 = *(const unsigned*)(G_H16 + (size_t)s1 * N + lane * 2);
                unsigned r2 = *(const unsigned*)(G_H16 + (size_t)s2 * N + lane * 2);
                unsigned r3 = *(const unsigned*)(G_H16 + (size_t)s3 * N + lane * 2);
                float2 a = __half22float2(*reinterpret_cast<__half2*>(&r0));
                float2 bb = __half22float2(*reinterpret_cast<__half2*>(&r1));
                float2 c = __half22float2(*reinterpret_cast<__half2*>(&r2));
                float2 d = __half22float2(*reinterpret_cast<__half2*>(&r3));
                acc[0] += (a.x + bb.x) + (c.x + d.x);
                acc[1] += (a.y + bb.y) + (c.y + d.y);
            }
        }
        for (; e < end; e++) {
            int s0 = g_csrc[e];
            if constexpr (VE == 4) {
                uint2 r0 = *(const uint2*)(G_H16 + (size_t)s0 * N + lane * 4);
                float2 a0 = __half22float2(*reinterpret_cast<__half2*>(&r0.x));
                float2 a1 = __half22float2(*reinterpret_cast<__half2*>(&r0.y));
                acc[0] += a0.x; acc[1] += a0.y; acc[2] += a1.x; acc[3] += a1.y;
            } else {
                unsigned r0 = *(const unsigned*)(G_H16 + (size_t)s0 * N + lane * 2);
                float2 a = __half22float2(*reinterpret_cast<__half2*>(&r0));
                acc[0] += a.x; acc[1] += a.y;
            }
        }
        float dd = g_dis[node];
        float v[VE];
#pragma unroll
        for (int i = 0; i < VE; i++) v[i] = fmaf(acc[i], dd, bv[i]);

        if constexpr (FINAL) {
            float* orow = out + (size_t)node * N + lane * VE;
#pragma unroll
            for (int i = 0; i < VE; i++) orow[i] = v[i];
        } else {
            float* orow = g_acc + (size_t)node * N + lane * VE;
            *(float4*)orow = make_float4(v[0], v[1], v[2], v[3]);
        }
    }
}

// ---------------- BN column stats over g_acc ----------------
__global__ __launch_bounds__(256) void k_stats() {
    __shared__ float ssum[256], ssq[256];
    int tid = threadIdx.x;
    int col = tid & 127;
    int rh = tid >> 7;
    int row0 = blockIdx.x * 32;
    float sum = 0.f, sq = 0.f;
    int rend = min(row0 + 32, NN);
    for (int r = row0 + rh; r < rend; r += 2) {
        float v = g_acc[(size_t)r * 128 + col];
        sum += v;
        sq += v * v;
    }
    ssum[tid] = sum;
    ssq[tid] = sq;
    __syncthreads();
    if (tid < 128) {
        atomicAdd(&g_stats[col], ssum[tid] + ssum[tid + 128]);
        atomicAdd(&g_stats[128 + col], ssq[tid] + ssq[tid + 128]);
    }
}

// ---------------- BN prep + apply ----------------
__global__ void k_bnprep(const float* __restrict__ g, const float* __restrict__ beta) {
    int c = threadIdx.x;  // 128 threads
    float m = g_stats[c] * (1.f / NN);
    float var = g_stats[128 + c] * (1.f / NN) - m * m;
    float sc = g[c] * rsqrtf(var + 1e-5f);
    g_stats[256 + c] = sc;
    g_stats[384 + c] = beta[c] - m * sc;
}

__global__ __launch_bounds__(256) void k_bnapply() {
    int row = blockIdx.x * 8 + (threadIdx.x >> 5);
    int lane = threadIdx.x & 31;
    if (row >= NN) return;
    float4 v = *reinterpret_cast<const float4*>(g_acc + (size_t)row * 128 + lane * 4);
    float4 sc = *reinterpret_cast<const float4*>(g_stats + 256 + lane * 4);
    float4 sh = *reinterpret_cast<const float4*>(g_stats + 384 + lane * 4);
    float y0 = fmaxf(fmaf(v.x, sc.x, sh.x), 0.f);
    float y1 = fmaxf(fmaf(v.y, sc.y, sh.y), 0.f);
    float y2 = fmaxf(fmaf(v.z, sc.z, sh.z), 0.f);
    float y3 = fmaxf(fmaf(v.w, sc.w, sh.w), 0.f);
    float sq = y0 * y0 + y1 * y1 + y2 * y2 + y3 * y3;
#pragma unroll
    for (int o = 16; o; o >>= 1) sq += __shfl_xor_sync(0xffffffffu, sq, o);
    float inv = 1.f / fmaxf(sqrtf(sq), 1e-12f);
    *reinterpret_cast<float4*>(g_x + (size_t)row * 128 + lane * 4) =
        make_float4(y0 * inv, y1 * inv, y2 * inv, y3 * inv);
}

// ---------------- BPR loss ----------------
__global__ __launch_bounds__(256) void k_loss(const float* __restrict__ xo,
                                              const int* __restrict__ uid,
                                              const int* __restrict__ pid,
                                              const int* __restrict__ nid) {
    int s = blockIdx.x * 8 + (threadIdx.x >> 5);
    int lane = threadIdx.x & 31;
    if (s >= NBATCH) return;
    const float* u = xo + (size_t)uid[s] * 64;
    const float* p = xo + (size_t)(USER_NUM + pid[s]) * 64;
    const float* nr = xo + (size_t)(USER_NUM + nid[s]) * 64;
    float ps = 0.f, ns = 0.f;
#pragma unroll
    for (int j = 0; j < 2; j++) {
        int c = lane + j * 32;
        float uv = u[c];
        ps += uv * p[c];
        ns += uv * nr[c];
    }
#pragma unroll
    for (int o = 16; o; o >>= 1) {
        ps += __shfl_xor_sync(0xffffffffu, ps, o);
        ns += __shfl_xor_sync(0xffffffffu, ns, o);
    }
    if (lane == 0) {
        float z = ps - ns;
        float ls = fminf(z, 0.f) - log1pf(expf(-fabsf(z)));
        atomicAdd(&g_loss, ls);
    }
}

__global__ void k_wloss(float* __restrict__ out) {
    out[0] = -g_loss * (1.f / NBATCH);
}

// ---------------- launch ----------------
extern "C" void kernel_launch(void* const* d_in, const int* in_sizes, int n_in,
                              void* d_out, int out_size) {
    const float* user_emb = (const float*)d_in[0];
    const float* item_emb = (const float*)d_in[1];
    const float* W0 = (const float*)d_in[2];
    const float* b0 = (const float*)d_in[3];
    const float* g0 = (const float*)d_in[4];
    const float* beta0 = (const float*)d_in[5];
    const float* W1 = (const float*)d_in[6];
    const float* b1 = (const float*)d_in[7];
    const float* g1 = (const float*)d_in[8];
    const float* beta1 = (const float*)d_in[9];
    const float* W2 = (const float*)d_in[10];
    const float* b2 = (const float*)d_in[11];
    const int* user_id = (const int*)d_in[12];
    const int* pos_item = (const int*)d_in[13];
    const int* neg_item = (const int*)d_in[14];
    const int* ei = (const int*)d_in[15];
    const int* src = ei;
    const int* dst = ei + NE;

    float* out = (float*)d_out;
    float* xout = out + 1;  // [rec_loss, x(150000x64)] -- only 4B aligned!

    const int EB = (NE + 255) / 256;
    const int AGGB = 2048;
    const int SB = (NN + 31) / 32;
    const int GB2 = (NN + 127) / 128;  // 1172

    // setup + CSR build
    k_zero<<<(NN + 255) / 256, 256>>>();
    k_deg<<<EB, 256>>>(dst);
    k_dis<<<(NN + 255) / 256, 256>>>();
    k_concat<<<(NN * 16 + 255) / 256, 256>>>(user_emb, item_emb);
    k_scan1<<<SCAN_B, 256>>>();
    k_scan2<<<1, 1024>>>();
    k_scan3<<<SCAN_B + 1, 256>>>();
    k_csrfill<<<EB, 256>>>(src, dst);

    // ---- layer 0: 64 -> 128 ----
    k_gemm2<64, 128, 8><<<GB2, 256>>>(W0);
    k_agg<128, false><<<AGGB, 256>>>(b0, nullptr);
    k_stats<<<SB, 256>>>();
    k_bnprep<<<1, 128>>>(g0, beta0);
    k_bnapply<<<(NN + 7) / 8, 256>>>();

    // ---- layer 1: 128 -> 128 ----
    k_zstats<<<1, 256>>>();
    k_gemm2<128, 128, 8><<<GB2, 256>>>(W1);
    k_agg<128, false><<<AGGB, 256>>>(b1, nullptr);
    k_stats<<<SB, 256>>>();
    k_bnprep<<<1, 128>>>(g1, beta1);
    k_bnapply<<<(NN + 7) / 8, 256>>>();

    // ---- layer 2: 128 -> 64 ----
    k_gemm2<128, 64, 4><<<GB2, 256>>>(W2);
    k_agg<64, true><<<AGGB, 256>>>(b2, xout);

    // ---- loss ----
    k_loss<<<(NBATCH + 7) / 8, 256>>>(xout, user_id, pos_item, neg_item);
    k_wloss<<<1, 1>>>(out);
}

// round 8
// speedup vs baseline: 5.7065x; 1.2798x over previous
#include <cuda_runtime.h>
#include <cuda_bf16.h>
#include <cuda_fp16.h>
#include <mma.h>
#include <math.h>

using namespace nvcuda;

#define USER_NUM 100000
#define ITEM_NUM 50000
#define NN 150000
#define NE 2400000
#define NBATCH 4096
#define SCAN_B ((NN + 255) / 256)   // 586

// Scratch (device globals; allocation is forbidden).
// Device symbols are referenced ONLY inside kernels (never as host-side args).
__device__ uint4 g_x16raw[150016 * 128 / 8];  // x * dis[row], fp16 (GEMM A)
__device__ uint4 g_h16raw[150016 * 128 / 8];  // hs = (x·dis)@W, fp16
__device__ uint4 g_w16raw[128 * 128 / 8];     // W fp16 (per layer)
#define G_X16 (reinterpret_cast<__half*>(g_x16raw))
#define G_H16 (reinterpret_cast<__half*>(g_h16raw))
#define G_W16 (reinterpret_cast<__half*>(g_w16raw))
__device__ float g_acc[150016 * 128];         // conv output (pre-BN, fp32)
__device__ float g_dis[150016];               // rsqrt(1+deg)
__device__ int   g_degi[150016];
__device__ int   g_rows[150016 + 16];         // CSR row offsets (by dst)
__device__ int   g_cursor[150016];
__device__ int   g_part[1024];
__device__ int   g_csrc[NE];                  // CSR column (src) ids
__device__ float g_stats[512];                // colsum | colsq | scale | shift
__device__ float g_loss;

// ---------------- setup ----------------

__global__ void k_zero() {
    int i = blockIdx.x * 256 + threadIdx.x;
    if (i < NN) g_degi[i] = 0;
    if (i < 256) g_stats[i] = 0.f;
    if (i == 0) g_loss = 0.f;
}

__global__ void k_zstats() { g_stats[threadIdx.x] = 0.f; }  // 256 threads

__global__ void k_deg(const int* __restrict__ dst) {
    int e = blockIdx.x * 256 + threadIdx.x;
    if (e < NE) atomicAdd(&g_degi[dst[e]], 1);
}

__global__ void k_dis() {
    int i = blockIdx.x * 256 + threadIdx.x;
    if (i < NN) g_dis[i] = rsqrtf(1.f + (float)g_degi[i]);
}

// concat + pre-scale by dis + fp16 convert. One uint4 (8 halves) per thread.
__global__ void k_concat16(const float* __restrict__ ue, const float* __restrict__ ie) {
    int i = blockIdx.x * 256 + threadIdx.x;  // uint4 index into x16 (K=64)
    const int TT = NN * 8;                   // 8 uint4 per 64-wide row
    if (i >= TT) return;
    int row = i >> 3;
    int col = (i & 7) * 8;
    float d = g_dis[row];
    const float* srcp = (row < USER_NUM) ? ue + (size_t)row * 64 + col
                                         : ie + (size_t)(row - USER_NUM) * 64 + col;
    float4 v0 = *(const float4*)srcp;
    float4 v1 = *(const float4*)(srcp + 4);
    __align__(16) __half2 h[4];
    h[0] = __floats2half2_rn(v0.x * d, v0.y * d);
    h[1] = __floats2half2_rn(v0.z * d, v0.w * d);
    h[2] = __floats2half2_rn(v1.x * d, v1.y * d);
    h[3] = __floats2half2_rn(v1.z * d, v1.w * d);
    *reinterpret_cast<uint4*>(G_X16 + (size_t)row * 64 + col) =
        *reinterpret_cast<const uint4*>(h);
}

// W fp32 -> fp16 (KN elements, KN/4 float4 reads)
__global__ void k_wconv(const float* __restrict__ W, int kn4) {
    int i = blockIdx.x * 256 + threadIdx.x;
    if (i >= kn4) return;
    float4 v = ((const float4*)W)[i];
    __align__(8) __half2 h[2];
    h[0] = __floats2half2_rn(v.x, v.y);
    h[1] = __floats2half2_rn(v.z, v.w);
    *reinterpret_cast<uint2*>(G_W16 + i * 4) = *reinterpret_cast<const uint2*>(h);
}

// ---------------- prefix scan ----------------

__global__ void k_scan1() {
    __shared__ int s[256];
    int tid = threadIdx.x;
    int i = blockIdx.x * 256 + tid;
    int v = (i < NN) ? g_degi[i] : 0;
    s[tid] = v;
    __syncthreads();
    for (int off = 1; off < 256; off <<= 1) {
        int t = (tid >= off) ? s[tid - off] : 0;
        __syncthreads();
        s[tid] += t;
        __syncthreads();
    }
    if (i < NN) g_rows[i] = s[tid] - v;
    if (tid == 255) g_part[blockIdx.x] = s[255];
}

__global__ void k_scan2() {  // 1 block, 1024 threads
    __shared__ int s[1024];
    int tid = threadIdx.x;
    int v = (tid < SCAN_B) ? g_part[tid] : 0;
    s[tid] = v;
    __syncthreads();
    for (int off = 1; off < 1024; off <<= 1) {
        int t = (tid >= off) ? s[tid - off] : 0;
        __syncthreads();
        s[tid] += t;
        __syncthreads();
    }
    if (tid < SCAN_B) g_part[tid] = s[tid] - v;
}

__global__ void k_scan3() {
    int i = blockIdx.x * 256 + threadIdx.x;
    if (i < NN) {
        int r = g_rows[i] + g_part[i >> 8];
        g_rows[i] = r;
        g_cursor[i] = r;
    }
    if (i == NN) g_rows[NN] = NE;
}

__global__ void k_csrfill(const int* __restrict__ src, const int* __restrict__ dst) {
    int e = blockIdx.x * 256 + threadIdx.x;
    if (e < NE) {
        int d = dst[e];
        int p = atomicAdd(&g_cursor[d], 1);
        g_csrc[p] = src[e];
    }
}

// ---------------- tensor-core GEMM: g_h16 = g_x16 @ g_w16 (A pre-scaled by dis) ----
// 128 rows x N per block, 8 warps, each warp 16 rows, wmma m16n16k16 fp16->fp32.
template <int K, int N>
__global__ __launch_bounds__(256) void k_gemmh() {
    __shared__ __half Ws[K * N];
    __shared__ float scr[8][256];
    const int tid = threadIdx.x;
    const int wid = tid >> 5;
    const int lane = tid & 31;

    for (int i = tid; i < K * N / 8; i += 256)
        ((uint4*)Ws)[i] = ((const uint4*)G_W16)[i];
    __syncthreads();

    const size_t rowbase = (size_t)blockIdx.x * 128 + wid * 16;
    const __half* A = G_X16 + rowbase * K;

    wmma::fragment<wmma::accumulator, 16, 16, 16, float> acc[N / 16];
#pragma unroll
    for (int j = 0; j < N / 16; j++) wmma::fill_fragment(acc[j], 0.f);

#pragma unroll
    for (int k0 = 0; k0 < K / 16; k0++) {
        wmma::fragment<wmma::matrix_a, 16, 16, 16, __half, wmma::row_major> a;
        wmma::load_matrix_sync(a, A + k0 * 16, K);
#pragma unroll
        for (int j = 0; j < N / 16; j++) {
            wmma::fragment<wmma::matrix_b, 16, 16, 16, __half, wmma::row_major> b;
            wmma::load_matrix_sync(b, Ws + k0 * 16 * N + j * 16, N);
            wmma::mma_sync(acc[j], a, b, acc[j]);
        }
    }

    __half* H = G_H16 + rowbase * N;
    const int r = lane >> 1;
    const int c0 = (lane & 1) * 8;
#pragma unroll
    for (int j = 0; j < N / 16; j++) {
        wmma::store_matrix_sync(scr[wid], acc[j], 16, wmma::mem_row_major);
        __syncwarp();
        __align__(16) __half2 h[4];
#pragma unroll
        for (int t = 0; t < 4; t++)
            h[t] = __floats2half2_rn(scr[wid][r * 16 + c0 + 2 * t],
                                     scr[wid][r * 16 + c0 + 2 * t + 1]);
        *reinterpret_cast<uint4*>(H + (size_t)r * N + j * 16 + c0) =
            *reinterpret_cast<const uint4*>(h);
        __syncwarp();
    }
}

// ---------------- CSR aggregation (4-edge unroll, fused BN stats) ----------------
// out[n] = dis[n]*(h[n] + sum_{e->n} h[src_e]) + b; h fp16, accum fp32.
template <int N, bool FINAL>
__global__ __launch_bounds__(256) void k_agg(const float* __restrict__ b,
                                             float* __restrict__ out) {
    constexpr int VE = N / 32;  // 4 or 2
    const int lane = threadIdx.x & 31;
    const int warp = threadIdx.x >> 5;
    __shared__ float s_sum[128], s_sq[128];
    if constexpr (!FINAL) {
        if (threadIdx.x < 128) { s_sum[threadIdx.x] = 0.f; s_sq[threadIdx.x] = 0.f; }
        __syncthreads();
    }
    float bv[VE], tsum[VE], tsq[VE];
#pragma unroll
    for (int i = 0; i < VE; i++) { bv[i] = b[lane * VE + i]; tsum[i] = 0.f; tsq[i] = 0.f; }

    for (int node = blockIdx.x * 8 + warp; node < NN; node += gridDim.x * 8) {
        float acc[VE];
        if constexpr (VE == 4) {
            uint2 raw = *(const uint2*)(G_H16 + (size_t)node * N + lane * 4);
            float2 f0 = __half22float2(*reinterpret_cast<__half2*>(&raw.x));
            float2 f1 = __half22float2(*reinterpret_cast<__half2*>(&raw.y));
            acc[0] = f0.x; acc[1] = f0.y; acc[2] = f1.x; acc[3] = f1.y;
        } else {
            unsigned raw = *(const unsigned*)(G_H16 + (size_t)node * N + lane * 2);
            float2 f = __half22float2(*reinterpret_cast<__half2*>(&raw));
            acc[0] = f.x; acc[1] = f.y;
        }
        int beg = g_rows[node], end = g_rows[node + 1];
        int e = beg;
        for (; e + 3 < end; e += 4) {  // 4 independent gathers -> MLP=4
            int s0 = g_csrc[e], s1 = g_csrc[e + 1], s2 = g_csrc[e + 2], s3 = g_csrc[e + 3];
            if constexpr (VE == 4) {
                uint2 r0 = *(const uint2*)(G_H16 + (size_t)s0 * N + lane * 4);
                uint2 r1 = *(const uint2*)(G_H16 + (size_t)s1 * N + lane * 4);
                uint2 r2 = *(const uint2*)(G_H16 + (size_t)s2 * N + lane * 4);
                uint2 r3 = *(const uint2*)(G_H16 + (size_t)s3 * N + lane * 4);
                float2 a0 = __half22float2(*reinterpret_cast<__half2*>(&r0.x));
                float2 a1 = __half22float2(*reinterpret_cast<__half2*>(&r0.y));
                float2 b0_ = __half22float2(*reinterpret_cast<__half2*>(&r1.x));
                float2 b1_ = __half22float2(*reinterpret_cast<__half2*>(&r1.y));
                float2 c0 = __half22float2(*reinterpret_cast<__half2*>(&r2.x));
                float2 c1 = __half22float2(*reinterpret_cast<__half2*>(&r2.y));
                float2 d0 = __half22float2(*reinterpret_cast<__half2*>(&r3.x));
                float2 d1 = __half22float2(*reinterpret_cast<__half2*>(&r3.y));
                acc[0] += (a0.x + b0_.x) + (c0.x + d0.x);
                acc[1] += (a0.y + b0_.y) + (c0.y + d0.y);
                acc[2] += (a1.x + b1_.x) + (c1.x + d1.x);
                acc[3] += (a1.y + b1_.y) + (c1.y + d1.y);
            } else {
                unsigned r0 = *(const unsigned*)(G_H16 + (size_t)s0 * N + lane * 2);
                unsigned r1 = *(const unsigned*)(G_H16 + (size_t)s1 * N + lane * 2);
                unsigned r2 = *(const unsigned*)(G_H16 + (size_t)s2 * N + lane * 2);
                unsigned r3 = *(const unsigned*)(G_H16 + (size_t)s3 * N + lane * 2);
                float2 a = __half22float2(*reinterpret_cast<__half2*>(&r0));
                float2 bb = __half22float2(*reinterpret_cast<__half2*>(&r1));
                float2 c = __half22float2(*reinterpret_cast<__half2*>(&r2));
                float2 d = __half22float2(*reinterpret_cast<__half2*>(&r3));
                acc[0] += (a.x + bb.x) + (c.x + d.x);
                acc[1] += (a.y + bb.y) + (c.y + d.y);
            }
        }
        for (; e < end; e++) {
            int s0 = g_csrc[e];
            if constexpr (VE == 4) {
                uint2 r0 = *(const uint2*)(G_H16 + (size_t)s0 * N + lane * 4);
                float2 a0 = __half22float2(*reinterpret_cast<__half2*>(&r0.x));
                float2 a1 = __half22float2(*reinterpret_cast<__half2*>(&r0.y));
                acc[0] += a0.x; acc[1] += a0.y; acc[2] += a1.x; acc[3] += a1.y;
            } else {
                unsigned r0 = *(const unsigned*)(G_H16 + (size_t)s0 * N + lane * 2);
                float2 a = __half22float2(*reinterpret_cast<__half2*>(&r0));
                acc[0] += a.x; acc[1] += a.y;
            }
        }
        float dd = g_dis[node];
        float v[VE];
#pragma unroll
        for (int i = 0; i < VE; i++) {
            v[i] = fmaf(acc[i], dd, bv[i]);
            if constexpr (!FINAL) { tsum[i] += v[i]; tsq[i] += v[i] * v[i]; }
        }

        if constexpr (FINAL) {
            float* orow = out + (size_t)node * N + lane * VE;
#pragma unroll
            for (int i = 0; i < VE; i++) orow[i] = v[i];
        } else {
            float* orow = g_acc + (size_t)node * N + lane * VE;
            *(float4*)orow = make_float4(v[0], v[1], v[2], v[3]);
        }
    }

    if constexpr (!FINAL) {
#pragma unroll
        for (int i = 0; i < VE; i++) {
            atomicAdd(&s_sum[lane * VE + i], tsum[i]);
            atomicAdd(&s_sq[lane * VE + i], tsq[i]);
        }
        __syncthreads();
        if (threadIdx.x < 128) {
            atomicAdd(&g_stats[threadIdx.x], s_sum[threadIdx.x]);
            atomicAdd(&g_stats[128 + threadIdx.x], s_sq[threadIdx.x]);
        }
    }
}

// ---------------- BN prep + apply ----------------
__global__ void k_bnprep(const float* __restrict__ g, const float* __restrict__ beta) {
    int c = threadIdx.x;  // 128 threads
    float m = g_stats[c] * (1.f / NN);
    float var = g_stats[128 + c] * (1.f / NN) - m * m;
    float sc = g[c] * rsqrtf(var + 1e-5f);
    g_stats[256 + c] = sc;
    g_stats[384 + c] = beta[c] - m * sc;
}

// BN affine + ReLU + row L2 norm; writes x16 = fp16(y * inv * dis[row])
__global__ __launch_bounds__(256) void k_bnapply() {
    int row = blockIdx.x * 8 + (threadIdx.x >> 5);
    int lane = threadIdx.x & 31;
    if (row >= NN) return;
    float4 v = *reinterpret_cast<const float4*>(g_acc + (size_t)row * 128 + lane * 4);
    float4 sc = *reinterpret_cast<const float4*>(g_stats + 256 + lane * 4);
    float4 sh = *reinterpret_cast<const float4*>(g_stats + 384 + lane * 4);
    float y0 = fmaxf(fmaf(v.x, sc.x, sh.x), 0.f);
    float y1 = fmaxf(fmaf(v.y, sc.y, sh.y), 0.f);
    float y2 = fmaxf(fmaf(v.z, sc.z, sh.z), 0.f);
    float y3 = fmaxf(fmaf(v.w, sc.w, sh.w), 0.f);
    float sq = y0 * y0 + y1 * y1 + y2 * y2 + y3 * y3;
#pragma unroll
    for (int o = 16; o; o >>= 1) sq += __shfl_xor_sync(0xffffffffu, sq, o);
    float inv = 1.f / fmaxf(sqrtf(sq), 1e-12f);
    inv *= g_dis[row];  // pre-scale for next GEMM
    __align__(8) __half2 h[2];
    h[0] = __floats2half2_rn(y0 * inv, y1 * inv);
    h[1] = __floats2half2_rn(y2 * inv, y3 * inv);
    *reinterpret_cast<uint2*>(G_X16 + (size_t)row * 128 + lane * 4) =
        *reinterpret_cast<const uint2*>(h);
}

// ---------------- BPR loss ----------------
__global__ __launch_bounds__(256) void k_loss(const float* __restrict__ xo,
                                              const int* __restrict__ uid,
                                              const int* __restrict__ pid,
                                              const int* __restrict__ nid) {
    int s = blockIdx.x * 8 + (threadIdx.x >> 5);
    int lane = threadIdx.x & 31;
    if (s >= NBATCH) return;
    const float* u = xo + (size_t)uid[s] * 64;
    const float* p = xo + (size_t)(USER_NUM + pid[s]) * 64;
    const float* nr = xo + (size_t)(USER_NUM + nid[s]) * 64;
    float ps = 0.f, ns = 0.f;
#pragma unroll
    for (int j = 0; j < 2; j++) {
        int c = lane + j * 32;
        float uv = u[c];
        ps += uv * p[c];
        ns += uv * nr[c];
    }
#pragma unroll
    for (int o = 16; o; o >>= 1) {
        ps += __shfl_xor_sync(0xffffffffu, ps, o);
        ns += __shfl_xor_sync(0xffffffffu, ns, o);
    }
    if (lane == 0) {
        float z = ps - ns;
        float ls = fminf(z, 0.f) - log1pf(expf(-fabsf(z)));
        atomicAdd(&g_loss, ls);
    }
}

__global__ void k_wloss(float* __restrict__ out) {
    out[0] = -g_loss * (1.f / NBATCH);
}

// ---------------- launch ----------------
extern "C" void kernel_launch(void* const* d_in, const int* in_sizes, int n_in,
                              void* d_out, int out_size) {
    const float* user_emb = (const float*)d_in[0];
    const float* item_emb = (const float*)d_in[1];
    const float* W0 = (const float*)d_in[2];
    const float* b0 = (const float*)d_in[3];
    const float* g0 = (const float*)d_in[4];
    const float* beta0 = (const float*)d_in[5];
    const float* W1 = (const float*)d_in[6];
    const float* b1 = (const float*)d_in[7];
    const float* g1 = (const float*)d_in[8];
    const float* beta1 = (const float*)d_in[9];
    const float* W2 = (const float*)d_in[10];
    const float* b2 = (const float*)d_in[11];
    const int* user_id = (const int*)d_in[12];
    const int* pos_item = (const int*)d_in[13];
    const int* neg_item = (const int*)d_in[14];
    const int* ei = (const int*)d_in[15];
    const int* src = ei;
    const int* dst = ei + NE;

    float* out = (float*)d_out;
    float* xout = out + 1;  // [rec_loss, x(150000x64)] -- only 4B aligned!

    const int EB = (NE + 255) / 256;
    const int AGGB = 2048;
    const int GB = (NN + 127) / 128;  // 1172

    // setup + CSR build
    k_zero<<<(NN + 255) / 256, 256>>>();
    k_deg<<<EB, 256>>>(dst);
    k_dis<<<(NN + 255) / 256, 256>>>();
    k_concat16<<<(NN * 8 + 255) / 256, 256>>>(user_emb, item_emb);
    k_scan1<<<SCAN_B, 256>>>();
    k_scan2<<<1, 1024>>>();
    k_scan3<<<SCAN_B + 1, 256>>>();
    k_csrfill<<<EB, 256>>>(src, dst);

    // ---- layer 0: 64 -> 128 ----
    k_wconv<<<(64 * 128 / 4 + 255) / 256, 256>>>(W0, 64 * 128 / 4);
    k_gemmh<64, 128><<<GB, 256>>>();
    k_agg<128, false><<<AGGB, 256>>>(b0, nullptr);
    k_bnprep<<<1, 128>>>(g0, beta0);
    k_bnapply<<<(NN + 7) / 8, 256>>>();

    // ---- layer 1: 128 -> 128 ----
    k_zstats<<<1, 256>>>();
    k_wconv<<<(128 * 128 / 4 + 255) / 256, 256>>>(W1, 128 * 128 / 4);
    k_gemmh<128, 128><<<GB, 256>>>();
    k_agg<128, false><<<AGGB, 256>>>(b1, nullptr);
    k_bnprep<<<1, 128>>>(g1, beta1);
    k_bnapply<<<(NN + 7) / 8, 256>>>();

    // ---- layer 2: 128 -> 64 ----
    k_wconv<<<(128 * 64 / 4 + 255) / 256, 256>>>(W2, 128 * 64 / 4);
    k_gemmh<128, 64><<<GB, 256>>>();
    k_agg<64, true><<<AGGB, 256>>>(b2, xout);

    // ---- loss ----
    k_loss<<<(NBATCH + 7) / 8, 256>>>(xout, user_id, pos_item, neg_item);
    k_wloss<<<1, 1>>>(out);
}